// round 8
// baseline (speedup 1.0000x reference)
#include <cuda_runtime.h>
#include <math.h>
#include <stdint.h>

#define BATCH 16
#define CIN   256
#define HW    4096      // 64*64
#define DOWN  1024      // 32*32
#define C8    32
#define C2    128
#define MCONV 192       // 32 + 32 + 128
#define NCHUNK 8        // l-chunks for column sum partials

// ---------------- scratch (device globals; no allocation allowed) ----------------
__device__ float g_w   [MCONV * CIN];
__device__ float g_bias[MCONV];
__device__ float g_q   [BATCH * C8 * HW];
__device__ float g_kc  [BATCH * C8 * HW];
__device__ float g_vc  [BATCH * C2 * HW];
__device__ float g_kp  [BATCH * C8 * DOWN];
__device__ float g_vp  [BATCH * C2 * DOWN];
__device__ float g_attn[(size_t)BATCH * HW * DOWN];   // 268 MB logits
__device__ float g_ps  [BATCH * NCHUNK * DOWN];       // partial sumexp
__device__ float g_csumr[BATCH * DOWN];
__device__ float g_app [BATCH * HW * C2];

// ---------------- helpers --------------------------------------------------------
__device__ __forceinline__ uint32_t f2tf32(float v) {
    uint32_t r;
    asm("cvt.rna.tf32.f32 %0, %1;" : "=r"(r) : "f"(v));
    return r;
}
__device__ __forceinline__ void split_tf32(float v, uint32_t& hi, uint32_t& lo) {
    hi = f2tf32(v);
    lo = f2tf32(v - __uint_as_float(hi));
}
__device__ __forceinline__ void mma_tf32(float* d, const uint32_t* a, const uint32_t* b) {
    asm volatile(
        "mma.sync.aligned.m16n8k8.row.col.f32.tf32.tf32.f32 "
        "{%0,%1,%2,%3}, {%4,%5,%6,%7}, {%8,%9}, {%0,%1,%2,%3};"
        : "+f"(d[0]), "+f"(d[1]), "+f"(d[2]), "+f"(d[3])
        : "r"(a[0]), "r"(a[1]), "r"(a[2]), "r"(a[3]), "r"(b[0]), "r"(b[1]));
}

// ---------------- K0: pack conv weights ------------------------------------------
__global__ void k_pack(const float* __restrict__ qw, const float* __restrict__ qb,
                       const float* __restrict__ kw, const float* __restrict__ kb,
                       const float* __restrict__ vw, const float* __restrict__ vb) {
    int i = blockIdx.x * 256 + threadIdx.x;
    if (i < MCONV * CIN) {
        int r = i >> 8, c = i & 255;
        float v;
        if (r < 32)      v = qw[r * CIN + c];
        else if (r < 64) v = kw[(r - 32) * CIN + c];
        else             v = vw[(r - 64) * CIN + c];
        g_w[i] = v;
    }
    if (i < MCONV)
        g_bias[i] = (i < 32) ? qb[i] : (i < 64) ? kb[i - 32] : vb[i - 64];
}

// ---------------- K1: fused q/k/v convs via mma tf32 -----------------------------
__global__ __launch_bounds__(256) void k_conv_mma(const float* __restrict__ x) {
    __shared__ float sA[64][36];    // W tile [m][k]
    __shared__ float sB[32][136];   // X tile [k][n]

    const int b  = blockIdx.z;
    const int m0 = blockIdx.y * 64;
    const int n0 = blockIdx.x * 128;
    const float* X = x + (size_t)b * CIN * HW;

    const int tid  = threadIdx.x;
    const int wid  = tid >> 5;
    const int lane = tid & 31;
    const int qid  = lane >> 2;
    const int qtr  = lane & 3;
    const int wm   = (wid >> 2) * 32;
    const int wn   = (wid & 3) * 32;

    float acc[2][4][4] = {};

    for (int k0 = 0; k0 < CIN; k0 += 32) {
        #pragma unroll
        for (int it = 0; it < 2; it++) {
            int f = tid + it * 256;
            int m = f >> 3, k4 = (f & 7) * 4;
            float4 a4 = *(const float4*)&g_w[(m0 + m) * CIN + k0 + k4];
            uint32_t* dp = (uint32_t*)&sA[m][k4];
            dp[0] = f2tf32(a4.x); dp[1] = f2tf32(a4.y);
            dp[2] = f2tf32(a4.z); dp[3] = f2tf32(a4.w);
        }
        #pragma unroll
        for (int it = 0; it < 4; it++) {
            int f = tid + it * 256;
            int kk = f >> 5, n4 = (f & 31) * 4;
            float4 b4 = *(const float4*)&X[(size_t)(k0 + kk) * HW + n0 + n4];
            uint32_t* dp = (uint32_t*)&sB[kk][n4];
            dp[0] = f2tf32(b4.x); dp[1] = f2tf32(b4.y);
            dp[2] = f2tf32(b4.z); dp[3] = f2tf32(b4.w);
        }
        __syncthreads();

        #pragma unroll
        for (int ks = 0; ks < 4; ks++) {
            const int kk = ks * 8;
            uint32_t af[2][4], bf[4][2];
            #pragma unroll
            for (int ma = 0; ma < 2; ma++) {
                int r = wm + ma * 16 + qid;
                af[ma][0] = __float_as_uint(sA[r    ][kk + qtr]);
                af[ma][1] = __float_as_uint(sA[r + 8][kk + qtr]);
                af[ma][2] = __float_as_uint(sA[r    ][kk + qtr + 4]);
                af[ma][3] = __float_as_uint(sA[r + 8][kk + qtr + 4]);
            }
            #pragma unroll
            for (int na = 0; na < 4; na++) {
                int c = wn + na * 8 + qid;
                bf[na][0] = __float_as_uint(sB[kk + qtr    ][c]);
                bf[na][1] = __float_as_uint(sB[kk + qtr + 4][c]);
            }
            #pragma unroll
            for (int ma = 0; ma < 2; ma++)
                #pragma unroll
                for (int na = 0; na < 4; na++)
                    mma_tf32(acc[ma][na], af[ma], bf[na]);
        }
        __syncthreads();
    }

    #pragma unroll
    for (int ma = 0; ma < 2; ma++) {
        #pragma unroll
        for (int half = 0; half < 2; half++) {
            int m = m0 + wm + ma * 16 + qid + half * 8;
            float bias = g_bias[m];
            float* dst;
            if (m < 32)      dst = g_q  + ((size_t)b * C8 + m)        * HW;
            else if (m < 64) dst = g_kc + ((size_t)b * C8 + (m - 32)) * HW;
            else             dst = g_vc + ((size_t)b * C2 + (m - 64)) * HW;
            #pragma unroll
            for (int na = 0; na < 4; na++) {
                int c = n0 + wn + na * 8 + 2 * qtr;
                float2 o;
                o.x = acc[ma][na][half * 2 + 0] + bias;
                o.y = acc[ma][na][half * 2 + 1] + bias;
                *(float2*)&dst[c] = o;
            }
        }
    }
}

// ---------------- K2: 2x2 max pool -----------------------------------------------
__global__ void k_pool() {
    int i = blockIdx.x * 256 + threadIdx.x;
    if (i >= BATCH * (C8 + C2) * DOWN) return;
    int b  = i / ((C8 + C2) * DOWN);
    int r  = i % ((C8 + C2) * DOWN);
    int ch = r / DOWN;
    int p  = r % DOWN;
    int ph = p >> 5, pw = p & 31;
    const float* src; float* dst;
    if (ch < C8) {
        src = g_kc + ((size_t)b * C8 + ch) * HW;
        dst = g_kp + ((size_t)b * C8 + ch) * DOWN;
    } else {
        ch -= C8;
        src = g_vc + ((size_t)b * C2 + ch) * HW;
        dst = g_vp + ((size_t)b * C2 + ch) * DOWN;
    }
    int base = (ph * 2) * 64 + pw * 2;
    float v0 = src[base], v1 = src[base + 1];
    float v2 = src[base + 64], v3 = src[base + 65];
    dst[p] = fmaxf(fmaxf(v0, v1), fmaxf(v2, v3));
}

// ---------------- K3a: attn = Q @ K^T via split-tf32 mma (fp32-accurate) ---------
// Tile 64l x 128j, K=32. a*b ~= hi_a*hi_b + lo_a*hi_b + hi_a*lo_b (3 MMAs).
__global__ __launch_bounds__(256) void k_attn_mma() {
    __shared__ float sQh[64][36],  sQl[64][36];
    __shared__ float sKh[128][36], sKl[128][36];

    const int b  = blockIdx.z;
    const int l0 = blockIdx.y * 64;
    const int j0 = blockIdx.x * 128;

    const float* Q  = g_q  + (size_t)b * (C8 * HW);    // [4096][32]
    const float* Km = g_kp + (size_t)b * (C8 * DOWN);  // [1024][32]

    const int tid  = threadIdx.x;
    const int wid  = tid >> 5;
    const int lane = tid & 31;
    const int qid  = lane >> 2;
    const int qtr  = lane & 3;
    const int wm   = (wid >> 2) * 32;   // 0 or 32
    const int wn   = (wid & 3) * 32;    // 0,32,64,96

    // stage Q (64x32) hi/lo
    #pragma unroll
    for (int it = 0; it < 2; it++) {
        int idx = tid + it * 256;
        int lr = idx >> 3, lc = (idx & 7) * 4;
        float4 v = *(const float4*)&Q[(size_t)(l0 + lr) * 32 + lc];
        uint32_t h, l;
        split_tf32(v.x, h, l); sQh[lr][lc + 0] = __uint_as_float(h); sQl[lr][lc + 0] = __uint_as_float(l);
        split_tf32(v.y, h, l); sQh[lr][lc + 1] = __uint_as_float(h); sQl[lr][lc + 1] = __uint_as_float(l);
        split_tf32(v.z, h, l); sQh[lr][lc + 2] = __uint_as_float(h); sQl[lr][lc + 2] = __uint_as_float(l);
        split_tf32(v.w, h, l); sQh[lr][lc + 3] = __uint_as_float(h); sQl[lr][lc + 3] = __uint_as_float(l);
    }
    // stage K (128x32) hi/lo
    #pragma unroll
    for (int it = 0; it < 4; it++) {
        int idx = tid + it * 256;
        int jr = idx >> 3, jc = (idx & 7) * 4;
        float4 v = *(const float4*)&Km[(size_t)(j0 + jr) * 32 + jc];
        uint32_t h, l;
        split_tf32(v.x, h, l); sKh[jr][jc + 0] = __uint_as_float(h); sKl[jr][jc + 0] = __uint_as_float(l);
        split_tf32(v.y, h, l); sKh[jr][jc + 1] = __uint_as_float(h); sKl[jr][jc + 1] = __uint_as_float(l);
        split_tf32(v.z, h, l); sKh[jr][jc + 2] = __uint_as_float(h); sKl[jr][jc + 2] = __uint_as_float(l);
        split_tf32(v.w, h, l); sKh[jr][jc + 3] = __uint_as_float(h); sKl[jr][jc + 3] = __uint_as_float(l);
    }
    __syncthreads();

    float acc[2][4][4] = {};
    #pragma unroll
    for (int ks = 0; ks < 4; ks++) {
        const int kk = ks * 8;
        uint32_t ah[2][4], al[2][4], bh[4][2], bl[4][2];
        #pragma unroll
        for (int ma = 0; ma < 2; ma++) {
            int r = wm + ma * 16 + qid;
            ah[ma][0] = __float_as_uint(sQh[r    ][kk + qtr]);
            ah[ma][1] = __float_as_uint(sQh[r + 8][kk + qtr]);
            ah[ma][2] = __float_as_uint(sQh[r    ][kk + qtr + 4]);
            ah[ma][3] = __float_as_uint(sQh[r + 8][kk + qtr + 4]);
            al[ma][0] = __float_as_uint(sQl[r    ][kk + qtr]);
            al[ma][1] = __float_as_uint(sQl[r + 8][kk + qtr]);
            al[ma][2] = __float_as_uint(sQl[r    ][kk + qtr + 4]);
            al[ma][3] = __float_as_uint(sQl[r + 8][kk + qtr + 4]);
        }
        #pragma unroll
        for (int na = 0; na < 4; na++) {
            int c = wn + na * 8 + qid;
            bh[na][0] = __float_as_uint(sKh[c][kk + qtr]);
            bh[na][1] = __float_as_uint(sKh[c][kk + qtr + 4]);
            bl[na][0] = __float_as_uint(sKl[c][kk + qtr]);
            bl[na][1] = __float_as_uint(sKl[c][kk + qtr + 4]);
        }
        #pragma unroll
        for (int ma = 0; ma < 2; ma++)
            #pragma unroll
            for (int na = 0; na < 4; na++) {
                mma_tf32(acc[ma][na], al[ma], bh[na]);   // lo*hi
                mma_tf32(acc[ma][na], ah[ma], bl[na]);   // hi*lo
                mma_tf32(acc[ma][na], ah[ma], bh[na]);   // hi*hi
            }
    }

    float* C = g_attn + ((size_t)b * HW + l0) * DOWN + j0;
    #pragma unroll
    for (int ma = 0; ma < 2; ma++) {
        int r = wm + ma * 16 + qid;
        #pragma unroll
        for (int na = 0; na < 4; na++) {
            int c = wn + na * 8 + 2 * qtr;
            float2 lo, hi;
            lo.x = acc[ma][na][0]; lo.y = acc[ma][na][1];
            hi.x = acc[ma][na][2]; hi.y = acc[ma][na][3];
            *(float2*)&C[(size_t)r * DOWN + c]       = lo;
            *(float2*)&C[(size_t)(r + 8) * DOWN + c] = hi;
        }
    }
}

// ---------------- K3b: per-column partial sum of exp (no max needed) -------------
__global__ void k_stats1() {
    const int b  = blockIdx.z;
    const int ck = blockIdx.y;
    const int j  = blockIdx.x * 256 + threadIdx.x;
    const int lsz = HW / NCHUNK;                    // 512
    const float* A = g_attn + (size_t)b * HW * DOWN + (size_t)ck * lsz * DOWN + j;
    float s0 = 0.f, s1 = 0.f, s2 = 0.f, s3 = 0.f;
    #pragma unroll 2
    for (int l = 0; l < lsz; l += 4) {
        s0 += __expf(A[(size_t)(l + 0) * DOWN]);
        s1 += __expf(A[(size_t)(l + 1) * DOWN]);
        s2 += __expf(A[(size_t)(l + 2) * DOWN]);
        s3 += __expf(A[(size_t)(l + 3) * DOWN]);
    }
    g_ps[(b * NCHUNK + ck) * DOWN + j] = (s0 + s1) + (s2 + s3);
}

__global__ void k_stats2() {
    const int b = blockIdx.y;
    const int j = blockIdx.x * 256 + threadIdx.x;
    float S = 0.f;
    #pragma unroll
    for (int c = 0; c < NCHUNK; c++)
        S += g_ps[(b * NCHUNK + c) * DOWN + j];
    g_csumr[b * DOWN + j] = 1.f / S;
}

// ---------------- K4: applied = softmax(attn) @ V via mma.sync tf32 --------------
__global__ __launch_bounds__(256, 2) void k_apply_mma() {
    __shared__ float sP[128][36];   // [l][j]
    __shared__ float sB[128][36];   // [c][j]

    const int b   = blockIdx.y;
    const int l0  = blockIdx.x * 128;
    const int tid = threadIdx.x;
    const int wid = tid >> 5;
    const int lane = tid & 31;
    const int qid = lane >> 2;
    const int qtr = lane & 3;
    const int wm = (wid >> 2) * 64;
    const int wn = (wid & 3) * 32;

    const float* A  = g_attn + ((size_t)b * HW + l0) * DOWN;
    const float* V  = g_vp   + (size_t)b * (C2 * DOWN);
    const float* cs = g_csumr + b * DOWN;

    float acc[4][4][4] = {};

    for (int j0 = 0; j0 < DOWN; j0 += 32) {
        #pragma unroll
        for (int it = 0; it < 4; it++) {
            int idx = tid + it * 256;
            int l = idx >> 3, jg = (idx & 7) * 4;
            float4 a4 = *(const float4*)&A[(size_t)l * DOWN + j0 + jg];
            uint32_t* dp = (uint32_t*)&sP[l][jg];
            dp[0] = f2tf32(__expf(a4.x));
            dp[1] = f2tf32(__expf(a4.y));
            dp[2] = f2tf32(__expf(a4.z));
            dp[3] = f2tf32(__expf(a4.w));
        }
        #pragma unroll
        for (int it = 0; it < 4; it++) {
            int idx = tid + it * 256;
            int c = idx & 127, j4 = idx >> 7;
            float4 s4 = *(const float4*)&cs[j0 + j4 * 4];
            uint32_t* dp = (uint32_t*)&sB[c][j4 * 4];
            dp[0] = f2tf32(V[(size_t)(j0 + j4 * 4 + 0) * C2 + c] * s4.x);
            dp[1] = f2tf32(V[(size_t)(j0 + j4 * 4 + 1) * C2 + c] * s4.y);
            dp[2] = f2tf32(V[(size_t)(j0 + j4 * 4 + 2) * C2 + c] * s4.z);
            dp[3] = f2tf32(V[(size_t)(j0 + j4 * 4 + 3) * C2 + c] * s4.w);
        }
        __syncthreads();

        #pragma unroll
        for (int ks = 0; ks < 4; ks++) {
            const int k0 = ks * 8;
            uint32_t af[4][4], bf[4][2];
            #pragma unroll
            for (int ma = 0; ma < 4; ma++) {
                int r = wm + ma * 16 + qid;
                af[ma][0] = __float_as_uint(sP[r    ][k0 + qtr]);
                af[ma][1] = __float_as_uint(sP[r + 8][k0 + qtr]);
                af[ma][2] = __float_as_uint(sP[r    ][k0 + qtr + 4]);
                af[ma][3] = __float_as_uint(sP[r + 8][k0 + qtr + 4]);
            }
            #pragma unroll
            for (int na = 0; na < 4; na++) {
                int c = wn + na * 8 + qid;
                bf[na][0] = __float_as_uint(sB[c][k0 + qtr]);
                bf[na][1] = __float_as_uint(sB[c][k0 + qtr + 4]);
            }
            #pragma unroll
            for (int ma = 0; ma < 4; ma++)
                #pragma unroll
                for (int na = 0; na < 4; na++)
                    mma_tf32(acc[ma][na], af[ma], bf[na]);
        }
        __syncthreads();
    }

    float* O = g_app + ((size_t)b * HW + l0) * C2;
    #pragma unroll
    for (int ma = 0; ma < 4; ma++) {
        int r = wm + ma * 16 + qid;
        #pragma unroll
        for (int na = 0; na < 4; na++) {
            int c = wn + na * 8 + 2 * qtr;
            float2 lo, hi;
            lo.x = acc[ma][na][0]; lo.y = acc[ma][na][1];
            hi.x = acc[ma][na][2]; hi.y = acc[ma][na][3];
            *(float2*)&O[(size_t)r * C2 + c]       = lo;
            *(float2*)&O[(size_t)(r + 8) * C2 + c] = hi;
        }
    }
}

// ---------------- K5: out = gamma*(W2 @ applied_r + b2) + x via mma tf32 ---------
__global__ __launch_bounds__(256) void k_out_mma(const float* __restrict__ w2,
                                                 const float* __restrict__ b2,
                                                 const float* __restrict__ gamma,
                                                 const float* __restrict__ x,
                                                 float* __restrict__ out) {
    __shared__ float sA[64][36];
    __shared__ float sB[32][136];

    const int b  = blockIdx.z;
    const int m0 = blockIdx.y * 64;
    const int n0 = blockIdx.x * 128;
    const float* Bm = g_app + (size_t)b * (HW * C2);   // viewed [128][4096]

    const int tid  = threadIdx.x;
    const int wid  = tid >> 5;
    const int lane = tid & 31;
    const int qid  = lane >> 2;
    const int qtr  = lane & 3;
    const int wm   = (wid >> 2) * 32;
    const int wn   = (wid & 3) * 32;

    float acc[2][4][4] = {};

    for (int k0 = 0; k0 < C2; k0 += 32) {
        #pragma unroll
        for (int it = 0; it < 2; it++) {
            int f = tid + it * 256;
            int m = f >> 3, k4 = (f & 7) * 4;
            float4 a4 = *(const float4*)&w2[(m0 + m) * C2 + k0 + k4];
            uint32_t* dp = (uint32_t*)&sA[m][k4];
            dp[0] = f2tf32(a4.x); dp[1] = f2tf32(a4.y);
            dp[2] = f2tf32(a4.z); dp[3] = f2tf32(a4.w);
        }
        #pragma unroll
        for (int it = 0; it < 4; it++) {
            int f = tid + it * 256;
            int kk = f >> 5, n4 = (f & 31) * 4;
            float4 b4 = *(const float4*)&Bm[(size_t)(k0 + kk) * HW + n0 + n4];
            uint32_t* dp = (uint32_t*)&sB[kk][n4];
            dp[0] = f2tf32(b4.x); dp[1] = f2tf32(b4.y);
            dp[2] = f2tf32(b4.z); dp[3] = f2tf32(b4.w);
        }
        __syncthreads();

        #pragma unroll
        for (int ks = 0; ks < 4; ks++) {
            const int kk = ks * 8;
            uint32_t af[2][4], bf[4][2];
            #pragma unroll
            for (int ma = 0; ma < 2; ma++) {
                int r = wm + ma * 16 + qid;
                af[ma][0] = __float_as_uint(sA[r    ][kk + qtr]);
                af[ma][1] = __float_as_uint(sA[r + 8][kk + qtr]);
                af[ma][2] = __float_as_uint(sA[r    ][kk + qtr + 4]);
                af[ma][3] = __float_as_uint(sA[r + 8][kk + qtr + 4]);
            }
            #pragma unroll
            for (int na = 0; na < 4; na++) {
                int c = wn + na * 8 + qid;
                bf[na][0] = __float_as_uint(sB[kk + qtr    ][c]);
                bf[na][1] = __float_as_uint(sB[kk + qtr + 4][c]);
            }
            #pragma unroll
            for (int ma = 0; ma < 2; ma++)
                #pragma unroll
                for (int na = 0; na < 4; na++)
                    mma_tf32(acc[ma][na], af[ma], bf[na]);
        }
        __syncthreads();
    }

    const float g = __ldg(gamma);
    #pragma unroll
    for (int ma = 0; ma < 2; ma++) {
        #pragma unroll
        for (int half = 0; half < 2; half++) {
            int m = m0 + wm + ma * 16 + qid + half * 8;
            float bias = b2[m];
            #pragma unroll
            for (int na = 0; na < 4; na++) {
                int c = n0 + wn + na * 8 + 2 * qtr;
                size_t base = ((size_t)b * 256 + m) * HW + c;
                float2 xi = *(const float2*)&x[base];
                float2 o;
                o.x = g * (acc[ma][na][half * 2 + 0] + bias) + xi.x;
                o.y = g * (acc[ma][na][half * 2 + 1] + bias) + xi.y;
                *(float2*)&out[base] = o;
            }
        }
    }
}

// ---------------- launch ---------------------------------------------------------
extern "C" void kernel_launch(void* const* d_in, const int* in_sizes, int n_in,
                              void* d_out, int out_size) {
    const float* x  = (const float*)d_in[0];
    const float* qw = (const float*)d_in[1];
    const float* qb = (const float*)d_in[2];
    const float* kw = (const float*)d_in[3];
    const float* kb = (const float*)d_in[4];
    const float* vw = (const float*)d_in[5];
    const float* vb = (const float*)d_in[6];
    const float* w2 = (const float*)d_in[7];
    const float* b2 = (const float*)d_in[8];
    const float* gm = (const float*)d_in[9];
    float* out = (float*)d_out;

    k_pack<<<(MCONV * CIN + 255) / 256, 256>>>(qw, qb, kw, kb, vw, vb);
    k_conv_mma<<<dim3(HW / 128, MCONV / 64, BATCH), 256>>>(x);
    k_pool<<<(BATCH * (C8 + C2) * DOWN + 255) / 256, 256>>>();
    k_attn_mma<<<dim3(DOWN / 128, HW / 64, BATCH), 256>>>();
    k_stats1<<<dim3(DOWN / 256, NCHUNK, BATCH), 256>>>();
    k_stats2<<<dim3(DOWN / 256, BATCH), 256>>>();
    k_apply_mma<<<dim3(HW / 128, BATCH), 256>>>();
    k_out_mma<<<dim3(HW / 128, 256 / 64, BATCH), 256>>>(w2, b2, gm, x, out);
}

// round 9
// speedup vs baseline: 1.0377x; 1.0377x over previous
#include <cuda_runtime.h>
#include <math.h>
#include <stdint.h>

#define BATCH 16
#define CIN   256
#define HW    4096      // 64*64
#define DOWN  1024      // 32*32
#define C8    32
#define C2    128
#define MCONV 192       // 32 + 32 + 128
#define NCHUNK 8        // l-chunks for column sum partials

// ---------------- scratch (device globals; no allocation allowed) ----------------
__device__ float g_w   [MCONV * CIN];
__device__ float g_bias[MCONV];
__device__ float g_q   [BATCH * C8 * HW];
__device__ float g_kc  [BATCH * C8 * HW];
__device__ float g_vc  [BATCH * C2 * HW];
__device__ float g_kp  [BATCH * C8 * DOWN];
__device__ float g_vp  [BATCH * C2 * DOWN];
__device__ float g_attn[(size_t)BATCH * HW * DOWN];   // 268 MB logits
__device__ float g_ps  [BATCH * NCHUNK * DOWN];       // partial sumexp
__device__ float g_csumr[BATCH * DOWN];
__device__ float g_app [BATCH * HW * C2];

// ---------------- helpers --------------------------------------------------------
__device__ __forceinline__ uint32_t f2tf32(float v) {
    uint32_t r;
    asm("cvt.rna.tf32.f32 %0, %1;" : "=r"(r) : "f"(v));
    return r;
}
__device__ __forceinline__ void mma_tf32(float* d, const uint32_t* a, const uint32_t* b) {
    asm volatile(
        "mma.sync.aligned.m16n8k8.row.col.f32.tf32.tf32.f32 "
        "{%0,%1,%2,%3}, {%4,%5,%6,%7}, {%8,%9}, {%0,%1,%2,%3};"
        : "+f"(d[0]), "+f"(d[1]), "+f"(d[2]), "+f"(d[3])
        : "r"(a[0]), "r"(a[1]), "r"(a[2]), "r"(a[3]), "r"(b[0]), "r"(b[1]));
}
#define FU(x) __float_as_uint(x)
#define UF(x) __uint_as_float(x)

// ---------------- K0: pack conv weights ------------------------------------------
__global__ void k_pack(const float* __restrict__ qw, const float* __restrict__ qb,
                       const float* __restrict__ kw, const float* __restrict__ kb,
                       const float* __restrict__ vw, const float* __restrict__ vb) {
    int i = blockIdx.x * 256 + threadIdx.x;
    if (i < MCONV * CIN) {
        int r = i >> 8, c = i & 255;
        float v;
        if (r < 32)      v = qw[r * CIN + c];
        else if (r < 64) v = kw[(r - 32) * CIN + c];
        else             v = vw[(r - 64) * CIN + c];
        g_w[i] = v;
    }
    if (i < MCONV)
        g_bias[i] = (i < 32) ? qb[i] : (i < 64) ? kb[i - 32] : vb[i - 64];
}

// ---------------- K1: fused q/k/v convs via mma tf32 -----------------------------
__global__ __launch_bounds__(256) void k_conv_mma(const float* __restrict__ x) {
    __shared__ float sA[64][36];    // W tile [m][k]
    __shared__ float sB[32][136];   // X tile [k][n]

    const int b  = blockIdx.z;
    const int m0 = blockIdx.y * 64;
    const int n0 = blockIdx.x * 128;
    const float* X = x + (size_t)b * CIN * HW;

    const int tid  = threadIdx.x;
    const int wid  = tid >> 5;
    const int lane = tid & 31;
    const int qid  = lane >> 2;
    const int qtr  = lane & 3;
    const int wm   = (wid >> 2) * 32;
    const int wn   = (wid & 3) * 32;

    float acc[2][4][4] = {};

    for (int k0 = 0; k0 < CIN; k0 += 32) {
        #pragma unroll
        for (int it = 0; it < 2; it++) {
            int f = tid + it * 256;
            int m = f >> 3, k4 = (f & 7) * 4;
            float4 a4 = *(const float4*)&g_w[(m0 + m) * CIN + k0 + k4];
            uint32_t* dp = (uint32_t*)&sA[m][k4];
            dp[0] = f2tf32(a4.x); dp[1] = f2tf32(a4.y);
            dp[2] = f2tf32(a4.z); dp[3] = f2tf32(a4.w);
        }
        #pragma unroll
        for (int it = 0; it < 4; it++) {
            int f = tid + it * 256;
            int kk = f >> 5, n4 = (f & 31) * 4;
            float4 b4 = *(const float4*)&X[(size_t)(k0 + kk) * HW + n0 + n4];
            uint32_t* dp = (uint32_t*)&sB[kk][n4];
            dp[0] = f2tf32(b4.x); dp[1] = f2tf32(b4.y);
            dp[2] = f2tf32(b4.z); dp[3] = f2tf32(b4.w);
        }
        __syncthreads();

        #pragma unroll
        for (int ks = 0; ks < 4; ks++) {
            const int kk = ks * 8;
            uint32_t af[2][4], bf[4][2];
            #pragma unroll
            for (int ma = 0; ma < 2; ma++) {
                int r = wm + ma * 16 + qid;
                af[ma][0] = FU(sA[r    ][kk + qtr]);
                af[ma][1] = FU(sA[r + 8][kk + qtr]);
                af[ma][2] = FU(sA[r    ][kk + qtr + 4]);
                af[ma][3] = FU(sA[r + 8][kk + qtr + 4]);
            }
            #pragma unroll
            for (int na = 0; na < 4; na++) {
                int c = wn + na * 8 + qid;
                bf[na][0] = FU(sB[kk + qtr    ][c]);
                bf[na][1] = FU(sB[kk + qtr + 4][c]);
            }
            #pragma unroll
            for (int ma = 0; ma < 2; ma++)
                #pragma unroll
                for (int na = 0; na < 4; na++)
                    mma_tf32(acc[ma][na], af[ma], bf[na]);
        }
        __syncthreads();
    }

    #pragma unroll
    for (int ma = 0; ma < 2; ma++) {
        #pragma unroll
        for (int half = 0; half < 2; half++) {
            int m = m0 + wm + ma * 16 + qid + half * 8;
            float bias = g_bias[m];
            float* dst;
            if (m < 32)      dst = g_q  + ((size_t)b * C8 + m)        * HW;
            else if (m < 64) dst = g_kc + ((size_t)b * C8 + (m - 32)) * HW;
            else             dst = g_vc + ((size_t)b * C2 + (m - 64)) * HW;
            #pragma unroll
            for (int na = 0; na < 4; na++) {
                int c = n0 + wn + na * 8 + 2 * qtr;
                float2 o;
                o.x = acc[ma][na][half * 2 + 0] + bias;
                o.y = acc[ma][na][half * 2 + 1] + bias;
                *(float2*)&dst[c] = o;
            }
        }
    }
}

// ---------------- K2: 2x2 max pool -----------------------------------------------
__global__ void k_pool() {
    int i = blockIdx.x * 256 + threadIdx.x;
    if (i >= BATCH * (C8 + C2) * DOWN) return;
    int b  = i / ((C8 + C2) * DOWN);
    int r  = i % ((C8 + C2) * DOWN);
    int ch = r / DOWN;
    int p  = r % DOWN;
    int ph = p >> 5, pw = p & 31;
    const float* src; float* dst;
    if (ch < C8) {
        src = g_kc + ((size_t)b * C8 + ch) * HW;
        dst = g_kp + ((size_t)b * C8 + ch) * DOWN;
    } else {
        ch -= C8;
        src = g_vc + ((size_t)b * C2 + ch) * HW;
        dst = g_vp + ((size_t)b * C2 + ch) * DOWN;
    }
    int base = (ph * 2) * 64 + pw * 2;
    float v0 = src[base], v1 = src[base + 1];
    float v2 = src[base + 64], v3 = src[base + 65];
    dst[p] = fmaxf(fmaxf(v0, v1), fmaxf(v2, v3));
}

// ---------------- K3a: attn = Q @ K^T, tile 64l x 128j, K=32 (fp32 SIMT) ---------
__global__ __launch_bounds__(256) void k_attn() {
    const int b  = blockIdx.z;
    const int l0 = blockIdx.y * 64;
    const int j0 = blockIdx.x * 128;

    const float* Q  = g_q  + (size_t)b * (C8 * HW);
    const float* Km = g_kp + (size_t)b * (C8 * DOWN);

    __shared__ float Qs[32][68];
    __shared__ float Ks[32][132];

    const int tid = threadIdx.x;
    const int tx = tid & 31;
    const int ty = tid >> 5;

    #pragma unroll
    for (int it = 0; it < 2; it++) {
        int idx = tid + it * 256;
        int lr = idx >> 3, lc = (idx & 7) * 4;
        float4 a = *(const float4*)&Q[(size_t)(l0 + lr) * 32 + lc];
        Qs[lc + 0][lr] = a.x; Qs[lc + 1][lr] = a.y;
        Qs[lc + 2][lr] = a.z; Qs[lc + 3][lr] = a.w;
    }
    #pragma unroll
    for (int it = 0; it < 4; it++) {
        int idx = tid + it * 256;
        int jr = idx >> 3, jc = (idx & 7) * 4;
        float4 k4 = *(const float4*)&Km[(size_t)(j0 + jr) * 32 + jc];
        Ks[jc + 0][jr] = k4.x; Ks[jc + 1][jr] = k4.y;
        Ks[jc + 2][jr] = k4.z; Ks[jc + 3][jr] = k4.w;
    }
    __syncthreads();

    float acc[8][4] = {};
    #pragma unroll
    for (int d = 0; d < 32; d++) {
        float a[8], bb[4];
        *(float4*)&a[0] = *(const float4*)&Qs[d][ty * 8];
        *(float4*)&a[4] = *(const float4*)&Qs[d][ty * 8 + 4];
        *(float4*)&bb[0] = *(const float4*)&Ks[d][tx * 4];
        #pragma unroll
        for (int i = 0; i < 8; i++)
            #pragma unroll
            for (int j = 0; j < 4; j++)
                acc[i][j] += a[i] * bb[j];
    }

    float* C = g_attn + ((size_t)b * HW + l0) * DOWN + j0;
    #pragma unroll
    for (int i = 0; i < 8; i++) {
        float4 o;
        o.x = acc[i][0]; o.y = acc[i][1]; o.z = acc[i][2]; o.w = acc[i][3];
        *(float4*)&C[(size_t)(ty * 8 + i) * DOWN + tx * 4] = o;
    }
}

// ---------------- K3b: per-column partial sum of exp (no max needed) -------------
__global__ void k_stats1() {
    const int b  = blockIdx.z;
    const int ck = blockIdx.y;
    const int j  = blockIdx.x * 256 + threadIdx.x;
    const int lsz = HW / NCHUNK;                    // 512
    const float* A = g_attn + (size_t)b * HW * DOWN + (size_t)ck * lsz * DOWN + j;
    float s0 = 0.f, s1 = 0.f, s2 = 0.f, s3 = 0.f;
    #pragma unroll 2
    for (int l = 0; l < lsz; l += 4) {
        s0 += __expf(A[(size_t)(l + 0) * DOWN]);
        s1 += __expf(A[(size_t)(l + 1) * DOWN]);
        s2 += __expf(A[(size_t)(l + 2) * DOWN]);
        s3 += __expf(A[(size_t)(l + 3) * DOWN]);
    }
    g_ps[(b * NCHUNK + ck) * DOWN + j] = (s0 + s1) + (s2 + s3);
}

__global__ void k_stats2() {
    const int b = blockIdx.y;
    const int j = blockIdx.x * 256 + threadIdx.x;
    float S = 0.f;
    #pragma unroll
    for (int c = 0; c < NCHUNK; c++)
        S += g_ps[(b * NCHUNK + c) * DOWN + j];
    g_csumr[b * DOWN + j] = 1.f / S;
}

// ---------------- K4: applied = softmax(attn) @ V via mma.sync tf32 --------------
// Permuted-k smem layout: chunk column j stored at PERM(j) = (j&3)*8 + (j>>2),
// so per-thread fragment elements are contiguous -> ld.shared.v4, conflict-free.
__global__ __launch_bounds__(256, 2) void k_apply_mma() {
    __shared__ float sP[128][36];   // [l][perm(j)]
    __shared__ float sB[128][36];   // [c][perm(j)]

    const int b   = blockIdx.y;
    const int l0  = blockIdx.x * 128;
    const int tid = threadIdx.x;
    const int wid = tid >> 5;
    const int lane = tid & 31;
    const int qid = lane >> 2;
    const int qtr = lane & 3;
    const int wm = (wid >> 2) * 64;
    const int wn = (wid & 3) * 32;

    const float* A  = g_attn + ((size_t)b * HW + l0) * DOWN;
    const float* V  = g_vp   + (size_t)b * (C2 * DOWN);
    const float* cs = g_csumr + b * DOWN;

    float acc[4][4][4] = {};

    for (int j0 = 0; j0 < DOWN; j0 += 32) {
        // stage P = exp(attn) into permuted layout: j = a*4 + e -> slot e*8 + a
        #pragma unroll
        for (int it = 0; it < 4; it++) {
            int idx = tid + it * 256;
            int l = idx >> 3, a = idx & 7;
            float4 a4 = *(const float4*)&A[(size_t)l * DOWN + j0 + a * 4];
            sP[l][a     ] = UF(f2tf32(__expf(a4.x)));
            sP[l][a + 8 ] = UF(f2tf32(__expf(a4.y)));
            sP[l][a + 16] = UF(f2tf32(__expf(a4.z)));
            sP[l][a + 24] = UF(f2tf32(__expf(a4.w)));
        }
        // stage B[c][perm(j)] = V[j][c] * csumr[j]; j = j4*4 + e -> slot e*8 + j4
        #pragma unroll
        for (int it = 0; it < 4; it++) {
            int idx = tid + it * 256;
            int c = idx & 127, j4 = idx >> 7;
            float4 s4 = *(const float4*)&cs[j0 + j4 * 4];
            sB[c][j4     ] = UF(f2tf32(V[(size_t)(j0 + j4 * 4 + 0) * C2 + c] * s4.x));
            sB[c][j4 + 8 ] = UF(f2tf32(V[(size_t)(j0 + j4 * 4 + 1) * C2 + c] * s4.y));
            sB[c][j4 + 16] = UF(f2tf32(V[(size_t)(j0 + j4 * 4 + 2) * C2 + c] * s4.z));
            sB[c][j4 + 24] = UF(f2tf32(V[(size_t)(j0 + j4 * 4 + 3) * C2 + c] * s4.w));
        }
        __syncthreads();

        // ks pairs: v4 at [qtr*8 + 4p] covers ks=2p (.x,.y) and ks=2p+1 (.z,.w)
        #pragma unroll
        for (int p = 0; p < 2; p++) {
            float4 Bv[4];
            #pragma unroll
            for (int na = 0; na < 4; na++) {
                int c = wn + na * 8 + qid;
                Bv[na] = *(const float4*)&sB[c][qtr * 8 + p * 4];
            }
            #pragma unroll
            for (int ma = 0; ma < 4; ma++) {
                int r = wm + ma * 16 + qid;
                float4 Ar  = *(const float4*)&sP[r    ][qtr * 8 + p * 4];
                float4 Ar8 = *(const float4*)&sP[r + 8][qtr * 8 + p * 4];
                uint32_t afA[4] = {FU(Ar.x), FU(Ar8.x), FU(Ar.y), FU(Ar8.y)};
                uint32_t afB[4] = {FU(Ar.z), FU(Ar8.z), FU(Ar.w), FU(Ar8.w)};
                #pragma unroll
                for (int na = 0; na < 4; na++) {
                    uint32_t bfA[2] = {FU(Bv[na].x), FU(Bv[na].y)};
                    uint32_t bfB[2] = {FU(Bv[na].z), FU(Bv[na].w)};
                    mma_tf32(acc[ma][na], afA, bfA);
                    mma_tf32(acc[ma][na], afB, bfB);
                }
            }
        }
        __syncthreads();
    }

    float* O = g_app + ((size_t)b * HW + l0) * C2;
    #pragma unroll
    for (int ma = 0; ma < 4; ma++) {
        int r = wm + ma * 16 + qid;
        #pragma unroll
        for (int na = 0; na < 4; na++) {
            int c = wn + na * 8 + 2 * qtr;
            float2 lo, hi;
            lo.x = acc[ma][na][0]; lo.y = acc[ma][na][1];
            hi.x = acc[ma][na][2]; hi.y = acc[ma][na][3];
            *(float2*)&O[(size_t)r * C2 + c]       = lo;
            *(float2*)&O[(size_t)(r + 8) * C2 + c] = hi;
        }
    }
}

// ---------------- K5: out = gamma*(W2 @ applied_r + b2) + x via mma tf32 ---------
__global__ __launch_bounds__(256) void k_out_mma(const float* __restrict__ w2,
                                                 const float* __restrict__ b2,
                                                 const float* __restrict__ gamma,
                                                 const float* __restrict__ x,
                                                 float* __restrict__ out) {
    __shared__ float sA[64][36];
    __shared__ float sB[32][136];

    const int b  = blockIdx.z;
    const int m0 = blockIdx.y * 64;
    const int n0 = blockIdx.x * 128;
    const float* Bm = g_app + (size_t)b * (HW * C2);   // viewed [128][4096]

    const int tid  = threadIdx.x;
    const int wid  = tid >> 5;
    const int lane = tid & 31;
    const int qid  = lane >> 2;
    const int qtr  = lane & 3;
    const int wm   = (wid >> 2) * 32;
    const int wn   = (wid & 3) * 32;

    float acc[2][4][4] = {};

    for (int k0 = 0; k0 < C2; k0 += 32) {
        #pragma unroll
        for (int it = 0; it < 2; it++) {
            int f = tid + it * 256;
            int m = f >> 3, k4 = (f & 7) * 4;
            float4 a4 = *(const float4*)&w2[(m0 + m) * C2 + k0 + k4];
            uint32_t* dp = (uint32_t*)&sA[m][k4];
            dp[0] = f2tf32(a4.x); dp[1] = f2tf32(a4.y);
            dp[2] = f2tf32(a4.z); dp[3] = f2tf32(a4.w);
        }
        #pragma unroll
        for (int it = 0; it < 4; it++) {
            int f = tid + it * 256;
            int kk = f >> 5, n4 = (f & 31) * 4;
            float4 b4 = *(const float4*)&Bm[(size_t)(k0 + kk) * HW + n0 + n4];
            uint32_t* dp = (uint32_t*)&sB[kk][n4];
            dp[0] = f2tf32(b4.x); dp[1] = f2tf32(b4.y);
            dp[2] = f2tf32(b4.z); dp[3] = f2tf32(b4.w);
        }
        __syncthreads();

        #pragma unroll
        for (int ks = 0; ks < 4; ks++) {
            const int kk = ks * 8;
            uint32_t af[2][4], bf[4][2];
            #pragma unroll
            for (int ma = 0; ma < 2; ma++) {
                int r = wm + ma * 16 + qid;
                af[ma][0] = FU(sA[r    ][kk + qtr]);
                af[ma][1] = FU(sA[r + 8][kk + qtr]);
                af[ma][2] = FU(sA[r    ][kk + qtr + 4]);
                af[ma][3] = FU(sA[r + 8][kk + qtr + 4]);
            }
            #pragma unroll
            for (int na = 0; na < 4; na++) {
                int c = wn + na * 8 + qid;
                bf[na][0] = FU(sB[kk + qtr    ][c]);
                bf[na][1] = FU(sB[kk + qtr + 4][c]);
            }
            #pragma unroll
            for (int ma = 0; ma < 2; ma++)
                #pragma unroll
                for (int na = 0; na < 4; na++)
                    mma_tf32(acc[ma][na], af[ma], bf[na]);
        }
        __syncthreads();
    }

    const float g = __ldg(gamma);
    #pragma unroll
    for (int ma = 0; ma < 2; ma++) {
        #pragma unroll
        for (int half = 0; half < 2; half++) {
            int m = m0 + wm + ma * 16 + qid + half * 8;
            float bias = b2[m];
            #pragma unroll
            for (int na = 0; na < 4; na++) {
                int c = n0 + wn + na * 8 + 2 * qtr;
                size_t base = ((size_t)b * 256 + m) * HW + c;
                float2 xi = *(const float2*)&x[base];
                float2 o;
                o.x = g * (acc[ma][na][half * 2 + 0] + bias) + xi.x;
                o.y = g * (acc[ma][na][half * 2 + 1] + bias) + xi.y;
                *(float2*)&out[base] = o;
            }
        }
    }
}

// ---------------- launch ---------------------------------------------------------
extern "C" void kernel_launch(void* const* d_in, const int* in_sizes, int n_in,
                              void* d_out, int out_size) {
    const float* x  = (const float*)d_in[0];
    const float* qw = (const float*)d_in[1];
    const float* qb = (const float*)d_in[2];
    const float* kw = (const float*)d_in[3];
    const float* kb = (const float*)d_in[4];
    const float* vw = (const float*)d_in[5];
    const float* vb = (const float*)d_in[6];
    const float* w2 = (const float*)d_in[7];
    const float* b2 = (const float*)d_in[8];
    const float* gm = (const float*)d_in[9];
    float* out = (float*)d_out;

    k_pack<<<(MCONV * CIN + 255) / 256, 256>>>(qw, qb, kw, kb, vw, vb);
    k_conv_mma<<<dim3(HW / 128, MCONV / 64, BATCH), 256>>>(x);
    k_pool<<<(BATCH * (C8 + C2) * DOWN + 255) / 256, 256>>>();
    k_attn<<<dim3(DOWN / 128, HW / 64, BATCH), 256>>>();
    k_stats1<<<dim3(DOWN / 256, NCHUNK, BATCH), 256>>>();
    k_stats2<<<dim3(DOWN / 256, BATCH), 256>>>();
    k_apply_mma<<<dim3(HW / 128, BATCH), 256>>>();
    k_out_mma<<<dim3(HW / 128, 256 / 64, BATCH), 256>>>(w2, b2, gm, x, out);
}

// round 10
// speedup vs baseline: 1.0599x; 1.0214x over previous
#include <cuda_runtime.h>
#include <cuda_bf16.h>
#include <math.h>
#include <stdint.h>

#define BATCH 16
#define CIN   256
#define HW    4096      // 64*64
#define DOWN  1024      // 32*32
#define C8    32
#define C2    128
#define MCONV 192       // 32 + 32 + 128
#define NCHUNK 8        // l-chunks for column sum partials

// ---------------- scratch (device globals; no allocation allowed) ----------------
__device__ float g_w   [MCONV * CIN];
__device__ float g_bias[MCONV];
__device__ float g_q   [BATCH * C8 * HW];
__device__ float g_kc  [BATCH * C8 * HW];
__device__ float g_vc  [BATCH * C2 * HW];
__device__ float g_kp  [BATCH * C8 * DOWN];
__device__ float g_vp  [BATCH * C2 * DOWN];
__device__ __nv_bfloat16 g_attn[(size_t)BATCH * HW * DOWN];  // 134 MB: P = exp(logit)
__device__ float g_ps  [BATCH * NCHUNK * DOWN];              // partial sums of P
__device__ float g_csumr[BATCH * DOWN];
__device__ float g_app [BATCH * HW * C2];

// ---------------- helpers --------------------------------------------------------
__device__ __forceinline__ uint32_t f2tf32(float v) {
    uint32_t r;
    asm("cvt.rna.tf32.f32 %0, %1;" : "=r"(r) : "f"(v));
    return r;
}
__device__ __forceinline__ void mma_tf32(float* d, const uint32_t* a, const uint32_t* b) {
    asm volatile(
        "mma.sync.aligned.m16n8k8.row.col.f32.tf32.tf32.f32 "
        "{%0,%1,%2,%3}, {%4,%5,%6,%7}, {%8,%9}, {%0,%1,%2,%3};"
        : "+f"(d[0]), "+f"(d[1]), "+f"(d[2]), "+f"(d[3])
        : "r"(a[0]), "r"(a[1]), "r"(a[2]), "r"(a[3]), "r"(b[0]), "r"(b[1]));
}
#define FU(x) __float_as_uint(x)

// ---------------- K0: pack conv weights ------------------------------------------
__global__ void k_pack(const float* __restrict__ qw, const float* __restrict__ qb,
                       const float* __restrict__ kw, const float* __restrict__ kb,
                       const float* __restrict__ vw, const float* __restrict__ vb) {
    int i = blockIdx.x * 256 + threadIdx.x;
    if (i < MCONV * CIN) {
        int r = i >> 8, c = i & 255;
        float v;
        if (r < 32)      v = qw[r * CIN + c];
        else if (r < 64) v = kw[(r - 32) * CIN + c];
        else             v = vw[(r - 64) * CIN + c];
        g_w[i] = v;
    }
    if (i < MCONV)
        g_bias[i] = (i < 32) ? qb[i] : (i < 64) ? kb[i - 32] : vb[i - 64];
}

// ---------------- K1: fused q/k/v convs via mma tf32 -----------------------------
__global__ __launch_bounds__(256) void k_conv_mma(const float* __restrict__ x) {
    __shared__ float sA[64][36];    // W tile [m][k]
    __shared__ float sB[32][136];   // X tile [k][n]

    const int b  = blockIdx.z;
    const int m0 = blockIdx.y * 64;
    const int n0 = blockIdx.x * 128;
    const float* X = x + (size_t)b * CIN * HW;

    const int tid  = threadIdx.x;
    const int wid  = tid >> 5;
    const int lane = tid & 31;
    const int qid  = lane >> 2;
    const int qtr  = lane & 3;
    const int wm   = (wid >> 2) * 32;
    const int wn   = (wid & 3) * 32;

    float acc[2][4][4] = {};

    for (int k0 = 0; k0 < CIN; k0 += 32) {
        #pragma unroll
        for (int it = 0; it < 2; it++) {
            int f = tid + it * 256;
            int m = f >> 3, k4 = (f & 7) * 4;
            float4 a4 = *(const float4*)&g_w[(m0 + m) * CIN + k0 + k4];
            uint32_t* dp = (uint32_t*)&sA[m][k4];
            dp[0] = f2tf32(a4.x); dp[1] = f2tf32(a4.y);
            dp[2] = f2tf32(a4.z); dp[3] = f2tf32(a4.w);
        }
        #pragma unroll
        for (int it = 0; it < 4; it++) {
            int f = tid + it * 256;
            int kk = f >> 5, n4 = (f & 31) * 4;
            float4 b4 = *(const float4*)&X[(size_t)(k0 + kk) * HW + n0 + n4];
            uint32_t* dp = (uint32_t*)&sB[kk][n4];
            dp[0] = f2tf32(b4.x); dp[1] = f2tf32(b4.y);
            dp[2] = f2tf32(b4.z); dp[3] = f2tf32(b4.w);
        }
        __syncthreads();

        #pragma unroll
        for (int ks = 0; ks < 4; ks++) {
            const int kk = ks * 8;
            uint32_t af[2][4], bf[4][2];
            #pragma unroll
            for (int ma = 0; ma < 2; ma++) {
                int r = wm + ma * 16 + qid;
                af[ma][0] = FU(sA[r    ][kk + qtr]);
                af[ma][1] = FU(sA[r + 8][kk + qtr]);
                af[ma][2] = FU(sA[r    ][kk + qtr + 4]);
                af[ma][3] = FU(sA[r + 8][kk + qtr + 4]);
            }
            #pragma unroll
            for (int na = 0; na < 4; na++) {
                int c = wn + na * 8 + qid;
                bf[na][0] = FU(sB[kk + qtr    ][c]);
                bf[na][1] = FU(sB[kk + qtr + 4][c]);
            }
            #pragma unroll
            for (int ma = 0; ma < 2; ma++)
                #pragma unroll
                for (int na = 0; na < 4; na++)
                    mma_tf32(acc[ma][na], af[ma], bf[na]);
        }
        __syncthreads();
    }

    #pragma unroll
    for (int ma = 0; ma < 2; ma++) {
        #pragma unroll
        for (int half = 0; half < 2; half++) {
            int m = m0 + wm + ma * 16 + qid + half * 8;
            float bias = g_bias[m];
            float* dst;
            if (m < 32)      dst = g_q  + ((size_t)b * C8 + m)        * HW;
            else if (m < 64) dst = g_kc + ((size_t)b * C8 + (m - 32)) * HW;
            else             dst = g_vc + ((size_t)b * C2 + (m - 64)) * HW;
            #pragma unroll
            for (int na = 0; na < 4; na++) {
                int c = n0 + wn + na * 8 + 2 * qtr;
                float2 o;
                o.x = acc[ma][na][half * 2 + 0] + bias;
                o.y = acc[ma][na][half * 2 + 1] + bias;
                *(float2*)&dst[c] = o;
            }
        }
    }
}

// ---------------- K2: 2x2 max pool -----------------------------------------------
__global__ void k_pool() {
    int i = blockIdx.x * 256 + threadIdx.x;
    if (i >= BATCH * (C8 + C2) * DOWN) return;
    int b  = i / ((C8 + C2) * DOWN);
    int r  = i % ((C8 + C2) * DOWN);
    int ch = r / DOWN;
    int p  = r % DOWN;
    int ph = p >> 5, pw = p & 31;
    const float* src; float* dst;
    if (ch < C8) {
        src = g_kc + ((size_t)b * C8 + ch) * HW;
        dst = g_kp + ((size_t)b * C8 + ch) * DOWN;
    } else {
        ch -= C8;
        src = g_vc + ((size_t)b * C2 + ch) * HW;
        dst = g_vp + ((size_t)b * C2 + ch) * DOWN;
    }
    int base = (ph * 2) * 64 + pw * 2;
    float v0 = src[base], v1 = src[base + 1];
    float v2 = src[base + 64], v3 = src[base + 65];
    dst[p] = fmaxf(fmaxf(v0, v1), fmaxf(v2, v3));
}

// ---------------- K3a: P = exp(Q @ K^T) stored bf16, tile 64l x 128j -------------
__global__ __launch_bounds__(256) void k_attn() {
    const int b  = blockIdx.z;
    const int l0 = blockIdx.y * 64;
    const int j0 = blockIdx.x * 128;

    const float* Q  = g_q  + (size_t)b * (C8 * HW);
    const float* Km = g_kp + (size_t)b * (C8 * DOWN);

    __shared__ float Qs[32][68];
    __shared__ float Ks[32][132];

    const int tid = threadIdx.x;
    const int tx = tid & 31;
    const int ty = tid >> 5;

    #pragma unroll
    for (int it = 0; it < 2; it++) {
        int idx = tid + it * 256;
        int lr = idx >> 3, lc = (idx & 7) * 4;
        float4 a = *(const float4*)&Q[(size_t)(l0 + lr) * 32 + lc];
        Qs[lc + 0][lr] = a.x; Qs[lc + 1][lr] = a.y;
        Qs[lc + 2][lr] = a.z; Qs[lc + 3][lr] = a.w;
    }
    #pragma unroll
    for (int it = 0; it < 4; it++) {
        int idx = tid + it * 256;
        int jr = idx >> 3, jc = (idx & 7) * 4;
        float4 k4 = *(const float4*)&Km[(size_t)(j0 + jr) * 32 + jc];
        Ks[jc + 0][jr] = k4.x; Ks[jc + 1][jr] = k4.y;
        Ks[jc + 2][jr] = k4.z; Ks[jc + 3][jr] = k4.w;
    }
    __syncthreads();

    float acc[8][4] = {};
    #pragma unroll
    for (int d = 0; d < 32; d++) {
        float a[8], bb[4];
        *(float4*)&a[0] = *(const float4*)&Qs[d][ty * 8];
        *(float4*)&a[4] = *(const float4*)&Qs[d][ty * 8 + 4];
        *(float4*)&bb[0] = *(const float4*)&Ks[d][tx * 4];
        #pragma unroll
        for (int i = 0; i < 8; i++)
            #pragma unroll
            for (int j = 0; j < 4; j++)
                acc[i][j] += a[i] * bb[j];
    }

    __nv_bfloat16* C = g_attn + ((size_t)b * HW + l0) * DOWN + j0;
    #pragma unroll
    for (int i = 0; i < 8; i++) {
        __nv_bfloat162 p0 = __floats2bfloat162_rn(__expf(acc[i][0]), __expf(acc[i][1]));
        __nv_bfloat162 p1 = __floats2bfloat162_rn(__expf(acc[i][2]), __expf(acc[i][3]));
        uint2 o;
        o.x = *(uint32_t*)&p0;
        o.y = *(uint32_t*)&p1;
        *(uint2*)&C[(size_t)(ty * 8 + i) * DOWN + tx * 4] = o;
    }
}

// ---------------- K3b: per-column partial sums of P (pure sum, bf16 in) ----------
__global__ void k_stats1() {
    const int b  = blockIdx.z;
    const int ck = blockIdx.y;
    const int j2 = blockIdx.x * 256 + threadIdx.x;   // column pair 0..511
    const int lsz = HW / NCHUNK;                     // 512
    const __nv_bfloat162* A = (const __nv_bfloat162*)(g_attn
        + (size_t)b * HW * DOWN + (size_t)ck * lsz * DOWN) + j2;
    float2 s0 = {0.f, 0.f}, s1 = {0.f, 0.f}, s2 = {0.f, 0.f}, s3 = {0.f, 0.f};
    #pragma unroll 2
    for (int l = 0; l < lsz; l += 4) {
        float2 a = __bfloat1622float2(A[(size_t)(l + 0) * (DOWN / 2)]);
        float2 bvv = __bfloat1622float2(A[(size_t)(l + 1) * (DOWN / 2)]);
        float2 c = __bfloat1622float2(A[(size_t)(l + 2) * (DOWN / 2)]);
        float2 d = __bfloat1622float2(A[(size_t)(l + 3) * (DOWN / 2)]);
        s0.x += a.x; s0.y += a.y;
        s1.x += bvv.x; s1.y += bvv.y;
        s2.x += c.x; s2.y += c.y;
        s3.x += d.x; s3.y += d.y;
    }
    float2 o;
    o.x = (s0.x + s1.x) + (s2.x + s3.x);
    o.y = (s0.y + s1.y) + (s2.y + s3.y);
    *(float2*)&g_ps[(b * NCHUNK + ck) * DOWN + j2 * 2] = o;
}

__global__ void k_stats2() {
    const int b = blockIdx.y;
    const int j = blockIdx.x * 256 + threadIdx.x;
    float S = 0.f;
    #pragma unroll
    for (int c = 0; c < NCHUNK; c++)
        S += g_ps[(b * NCHUNK + c) * DOWN + j];
    g_csumr[b * DOWN + j] = 1.f / S;
}

// ---------------- K4: applied = P @ (V/S) via mma.sync tf32 ----------------------
// P already exp'd in bf16; bf16->f32 is exact and tf32-valid (no cvt needed).
// Permuted-k smem layout: column j at PERM(j) = (j&3)*8 + (j>>2).
__global__ __launch_bounds__(256, 2) void k_apply_mma() {
    __shared__ float sP[128][36];   // [l][perm(j)]
    __shared__ float sB[128][36];   // [c][perm(j)]

    const int b   = blockIdx.y;
    const int l0  = blockIdx.x * 128;
    const int tid = threadIdx.x;
    const int wid = tid >> 5;
    const int lane = tid & 31;
    const int qid = lane >> 2;
    const int qtr = lane & 3;
    const int wm = (wid >> 2) * 64;
    const int wn = (wid & 3) * 32;

    const __nv_bfloat162* A = (const __nv_bfloat162*)(g_attn + ((size_t)b * HW + l0) * DOWN);
    const float* V  = g_vp   + (size_t)b * (C2 * DOWN);
    const float* cs = g_csumr + b * DOWN;

    float acc[4][4][4] = {};

    for (int j0 = 0; j0 < DOWN; j0 += 32) {
        // stage P (bf16 -> f32, exact): j = a*4 + e -> slot e*8 + a
        #pragma unroll
        for (int it = 0; it < 4; it++) {
            int idx = tid + it * 256;
            int l = idx >> 3, a = idx & 7;
            const __nv_bfloat162* src = A + (size_t)l * (DOWN / 2) + (j0 >> 1) + a * 2;
            float2 f01 = __bfloat1622float2(src[0]);
            float2 f23 = __bfloat1622float2(src[1]);
            sP[l][a     ] = f01.x;
            sP[l][a + 8 ] = f01.y;
            sP[l][a + 16] = f23.x;
            sP[l][a + 24] = f23.y;
        }
        // stage B[c][perm(j)] = V[j][c] * csumr[j]; j = j4*4 + e -> slot e*8 + j4
        #pragma unroll
        for (int it = 0; it < 4; it++) {
            int idx = tid + it * 256;
            int c = idx & 127, j4 = idx >> 7;
            float4 s4 = *(const float4*)&cs[j0 + j4 * 4];
            sB[c][j4     ] = __uint_as_float(f2tf32(V[(size_t)(j0 + j4 * 4 + 0) * C2 + c] * s4.x));
            sB[c][j4 + 8 ] = __uint_as_float(f2tf32(V[(size_t)(j0 + j4 * 4 + 1) * C2 + c] * s4.y));
            sB[c][j4 + 16] = __uint_as_float(f2tf32(V[(size_t)(j0 + j4 * 4 + 2) * C2 + c] * s4.z));
            sB[c][j4 + 24] = __uint_as_float(f2tf32(V[(size_t)(j0 + j4 * 4 + 3) * C2 + c] * s4.w));
        }
        __syncthreads();

        #pragma unroll
        for (int p = 0; p < 2; p++) {
            float4 Bv[4];
            #pragma unroll
            for (int na = 0; na < 4; na++) {
                int c = wn + na * 8 + qid;
                Bv[na] = *(const float4*)&sB[c][qtr * 8 + p * 4];
            }
            #pragma unroll
            for (int ma = 0; ma < 4; ma++) {
                int r = wm + ma * 16 + qid;
                float4 Ar  = *(const float4*)&sP[r    ][qtr * 8 + p * 4];
                float4 Ar8 = *(const float4*)&sP[r + 8][qtr * 8 + p * 4];
                uint32_t afA[4] = {FU(Ar.x), FU(Ar8.x), FU(Ar.y), FU(Ar8.y)};
                uint32_t afB[4] = {FU(Ar.z), FU(Ar8.z), FU(Ar.w), FU(Ar8.w)};
                #pragma unroll
                for (int na = 0; na < 4; na++) {
                    uint32_t bfA[2] = {FU(Bv[na].x), FU(Bv[na].y)};
                    uint32_t bfB[2] = {FU(Bv[na].z), FU(Bv[na].w)};
                    mma_tf32(acc[ma][na], afA, bfA);
                    mma_tf32(acc[ma][na], afB, bfB);
                }
            }
        }
        __syncthreads();
    }

    float* O = g_app + ((size_t)b * HW + l0) * C2;
    #pragma unroll
    for (int ma = 0; ma < 4; ma++) {
        int r = wm + ma * 16 + qid;
        #pragma unroll
        for (int na = 0; na < 4; na++) {
            int c = wn + na * 8 + 2 * qtr;
            float2 lo, hi;
            lo.x = acc[ma][na][0]; lo.y = acc[ma][na][1];
            hi.x = acc[ma][na][2]; hi.y = acc[ma][na][3];
            *(float2*)&O[(size_t)r * C2 + c]       = lo;
            *(float2*)&O[(size_t)(r + 8) * C2 + c] = hi;
        }
    }
}

// ---------------- K5: out = gamma*(W2 @ applied_r + b2) + x via mma tf32 ---------
__global__ __launch_bounds__(256) void k_out_mma(const float* __restrict__ w2,
                                                 const float* __restrict__ b2,
                                                 const float* __restrict__ gamma,
                                                 const float* __restrict__ x,
                                                 float* __restrict__ out) {
    __shared__ float sA[64][36];
    __shared__ float sB[32][136];

    const int b  = blockIdx.z;
    const int m0 = blockIdx.y * 64;
    const int n0 = blockIdx.x * 128;
    const float* Bm = g_app + (size_t)b * (HW * C2);   // viewed [128][4096]

    const int tid  = threadIdx.x;
    const int wid  = tid >> 5;
    const int lane = tid & 31;
    const int qid  = lane >> 2;
    const int qtr  = lane & 3;
    const int wm   = (wid >> 2) * 32;
    const int wn   = (wid & 3) * 32;

    float acc[2][4][4] = {};

    for (int k0 = 0; k0 < C2; k0 += 32) {
        #pragma unroll
        for (int it = 0; it < 2; it++) {
            int f = tid + it * 256;
            int m = f >> 3, k4 = (f & 7) * 4;
            float4 a4 = *(const float4*)&w2[(m0 + m) * C2 + k0 + k4];
            uint32_t* dp = (uint32_t*)&sA[m][k4];
            dp[0] = f2tf32(a4.x); dp[1] = f2tf32(a4.y);
            dp[2] = f2tf32(a4.z); dp[3] = f2tf32(a4.w);
        }
        #pragma unroll
        for (int it = 0; it < 4; it++) {
            int f = tid + it * 256;
            int kk = f >> 5, n4 = (f & 31) * 4;
            float4 b4 = *(const float4*)&Bm[(size_t)(k0 + kk) * HW + n0 + n4];
            uint32_t* dp = (uint32_t*)&sB[kk][n4];
            dp[0] = f2tf32(b4.x); dp[1] = f2tf32(b4.y);
            dp[2] = f2tf32(b4.z); dp[3] = f2tf32(b4.w);
        }
        __syncthreads();

        #pragma unroll
        for (int ks = 0; ks < 4; ks++) {
            const int kk = ks * 8;
            uint32_t af[2][4], bf[4][2];
            #pragma unroll
            for (int ma = 0; ma < 2; ma++) {
                int r = wm + ma * 16 + qid;
                af[ma][0] = FU(sA[r    ][kk + qtr]);
                af[ma][1] = FU(sA[r + 8][kk + qtr]);
                af[ma][2] = FU(sA[r    ][kk + qtr + 4]);
                af[ma][3] = FU(sA[r + 8][kk + qtr + 4]);
            }
            #pragma unroll
            for (int na = 0; na < 4; na++) {
                int c = wn + na * 8 + qid;
                bf[na][0] = FU(sB[kk + qtr    ][c]);
                bf[na][1] = FU(sB[kk + qtr + 4][c]);
            }
            #pragma unroll
            for (int ma = 0; ma < 2; ma++)
                #pragma unroll
                for (int na = 0; na < 4; na++)
                    mma_tf32(acc[ma][na], af[ma], bf[na]);
        }
        __syncthreads();
    }

    const float g = __ldg(gamma);
    #pragma unroll
    for (int ma = 0; ma < 2; ma++) {
        #pragma unroll
        for (int half = 0; half < 2; half++) {
            int m = m0 + wm + ma * 16 + qid + half * 8;
            float bias = b2[m];
            #pragma unroll
            for (int na = 0; na < 4; na++) {
                int c = n0 + wn + na * 8 + 2 * qtr;
                size_t base = ((size_t)b * 256 + m) * HW + c;
                float2 xi = *(const float2*)&x[base];
                float2 o;
                o.x = g * (acc[ma][na][half * 2 + 0] + bias) + xi.x;
                o.y = g * (acc[ma][na][half * 2 + 1] + bias) + xi.y;
                *(float2*)&out[base] = o;
            }
        }
    }
}

// ---------------- launch ---------------------------------------------------------
extern "C" void kernel_launch(void* const* d_in, const int* in_sizes, int n_in,
                              void* d_out, int out_size) {
    const float* x  = (const float*)d_in[0];
    const float* qw = (const float*)d_in[1];
    const float* qb = (const float*)d_in[2];
    const float* kw = (const float*)d_in[3];
    const float* kb = (const float*)d_in[4];
    const float* vw = (const float*)d_in[5];
    const float* vb = (const float*)d_in[6];
    const float* w2 = (const float*)d_in[7];
    const float* b2 = (const float*)d_in[8];
    const float* gm = (const float*)d_in[9];
    float* out = (float*)d_out;

    k_pack<<<(MCONV * CIN + 255) / 256, 256>>>(qw, qb, kw, kb, vw, vb);
    k_conv_mma<<<dim3(HW / 128, MCONV / 64, BATCH), 256>>>(x);
    k_pool<<<(BATCH * (C8 + C2) * DOWN + 255) / 256, 256>>>();
    k_attn<<<dim3(DOWN / 128, HW / 64, BATCH), 256>>>();
    k_stats1<<<dim3(DOWN / 2 / 256, NCHUNK, BATCH), 256>>>();
    k_stats2<<<dim3(DOWN / 256, BATCH), 256>>>();
    k_apply_mma<<<dim3(HW / 128, BATCH), 256>>>();
    k_out_mma<<<dim3(HW / 128, 256 / 64, BATCH), 256>>>(w2, b2, gm, x, out);
}

// round 11
// speedup vs baseline: 1.1224x; 1.0590x over previous
#include <cuda_runtime.h>
#include <cuda_bf16.h>
#include <math.h>
#include <stdint.h>

#define BATCH 16
#define CIN   256
#define HW    4096      // 64*64
#define DOWN  1024      // 32*32
#define C8    32
#define C2    128
#define MCONV 192       // 32 + 32 + 128
#define NCHUNK 8        // l-chunks for column sum partials

// ---------------- scratch (device globals; no allocation allowed) ----------------
__device__ float g_w   [MCONV * CIN];
__device__ float g_bias[MCONV];
__device__ float g_q   [BATCH * C8 * HW];
__device__ float g_kp  [BATCH * C8 * DOWN];
__device__ float g_vp  [BATCH * C2 * DOWN];
__device__ __nv_bfloat16 g_attn[(size_t)BATCH * HW * DOWN];  // 134 MB: P = exp(logit)
__device__ float g_ps  [BATCH * NCHUNK * DOWN];              // partial sums of P
__device__ float g_csumr[BATCH * DOWN];
__device__ float g_app [BATCH * HW * C2];

// ---------------- helpers --------------------------------------------------------
__device__ __forceinline__ uint32_t f2tf32(float v) {
    uint32_t r;
    asm("cvt.rna.tf32.f32 %0, %1;" : "=r"(r) : "f"(v));
    return r;
}
__device__ __forceinline__ void mma_tf32(float* d, const uint32_t* a, const uint32_t* b) {
    asm volatile(
        "mma.sync.aligned.m16n8k8.row.col.f32.tf32.tf32.f32 "
        "{%0,%1,%2,%3}, {%4,%5,%6,%7}, {%8,%9}, {%0,%1,%2,%3};"
        : "+f"(d[0]), "+f"(d[1]), "+f"(d[2]), "+f"(d[3])
        : "r"(a[0]), "r"(a[1]), "r"(a[2]), "r"(a[3]), "r"(b[0]), "r"(b[1]));
}
#define FU(x) __float_as_uint(x)

// ---------------- K0: pack conv weights ------------------------------------------
__global__ void k_pack(const float* __restrict__ qw, const float* __restrict__ qb,
                       const float* __restrict__ kw, const float* __restrict__ kb,
                       const float* __restrict__ vw, const float* __restrict__ vb) {
    int i = blockIdx.x * 256 + threadIdx.x;
    if (i < MCONV * CIN) {
        int r = i >> 8, c = i & 255;
        float v;
        if (r < 32)      v = qw[r * CIN + c];
        else if (r < 64) v = kw[(r - 32) * CIN + c];
        else             v = vw[(r - 64) * CIN + c];
        g_w[i] = v;
    }
    if (i < MCONV)
        g_bias[i] = (i < 32) ? qb[i] : (i < 64) ? kb[i - 32] : vb[i - 64];
}

// ---------------- K1: fused q/k/v convs + INLINE 2x2 MAXPOOL for k/v -------------
// n-tile of 128 spans exactly spatial rows {h0, h0+1}, h0 even, so every 2x2 pool
// window lives inside one CTA. q rows store full-res; k/v rows store pooled only.
__global__ __launch_bounds__(256) void k_conv_mma(const float* __restrict__ x) {
    __shared__ float sA[64][36];    // W tile [m][k]
    __shared__ float sB[32][136];   // X tile [k][n]
    __shared__ float sPool[64][36]; // lower-half pair-max exchange

    const int b  = blockIdx.z;
    const int m0 = blockIdx.y * 64;
    const int n0 = blockIdx.x * 128;
    const float* X = x + (size_t)b * CIN * HW;

    const int tid  = threadIdx.x;
    const int wid  = tid >> 5;
    const int lane = tid & 31;
    const int qid  = lane >> 2;
    const int qtr  = lane & 3;
    const int wm   = (wid >> 2) * 32;
    const int wn   = (wid & 3) * 32;

    float acc[2][4][4] = {};

    for (int k0 = 0; k0 < CIN; k0 += 32) {
        #pragma unroll
        for (int it = 0; it < 2; it++) {
            int f = tid + it * 256;
            int m = f >> 3, k4 = (f & 7) * 4;
            float4 a4 = *(const float4*)&g_w[(m0 + m) * CIN + k0 + k4];
            uint32_t* dp = (uint32_t*)&sA[m][k4];
            dp[0] = f2tf32(a4.x); dp[1] = f2tf32(a4.y);
            dp[2] = f2tf32(a4.z); dp[3] = f2tf32(a4.w);
        }
        #pragma unroll
        for (int it = 0; it < 4; it++) {
            int f = tid + it * 256;
            int kk = f >> 5, n4 = (f & 31) * 4;
            float4 b4 = *(const float4*)&X[(size_t)(k0 + kk) * HW + n0 + n4];
            uint32_t* dp = (uint32_t*)&sB[kk][n4];
            dp[0] = f2tf32(b4.x); dp[1] = f2tf32(b4.y);
            dp[2] = f2tf32(b4.z); dp[3] = f2tf32(b4.w);
        }
        __syncthreads();

        #pragma unroll
        for (int ks = 0; ks < 4; ks++) {
            const int kk = ks * 8;
            uint32_t af[2][4], bf[4][2];
            #pragma unroll
            for (int ma = 0; ma < 2; ma++) {
                int r = wm + ma * 16 + qid;
                af[ma][0] = FU(sA[r    ][kk + qtr]);
                af[ma][1] = FU(sA[r + 8][kk + qtr]);
                af[ma][2] = FU(sA[r    ][kk + qtr + 4]);
                af[ma][3] = FU(sA[r + 8][kk + qtr + 4]);
            }
            #pragma unroll
            for (int na = 0; na < 4; na++) {
                int c = wn + na * 8 + qid;
                bf[na][0] = FU(sB[kk + qtr    ][c]);
                bf[na][1] = FU(sB[kk + qtr + 4][c]);
            }
            #pragma unroll
            for (int ma = 0; ma < 2; ma++)
                #pragma unroll
                for (int na = 0; na < 4; na++)
                    mma_tf32(acc[ma][na], af[ma], bf[na]);
        }
        __syncthreads();
    }

    // ---- epilogue phase 1: q direct stores + lower-half (h0 row) pool partials --
    #pragma unroll
    for (int ma = 0; ma < 2; ma++) {
        #pragma unroll
        for (int half = 0; half < 2; half++) {
            int rl = wm + ma * 16 + qid + half * 8;   // row in tile 0..63
            int m  = m0 + rl;
            float bias = g_bias[m];
            if (m < 32) {
                float* dst = g_q + ((size_t)b * C8 + m) * HW;
                #pragma unroll
                for (int na = 0; na < 4; na++) {
                    int c = n0 + wn + na * 8 + 2 * qtr;
                    float2 o;
                    o.x = acc[ma][na][half * 2 + 0] + bias;
                    o.y = acc[ma][na][half * 2 + 1] + bias;
                    *(float2*)&dst[c] = o;
                }
            } else if (wn < 64) {
                #pragma unroll
                for (int na = 0; na < 4; na++) {
                    float vx = acc[ma][na][half * 2 + 0] + bias;
                    float vy = acc[ma][na][half * 2 + 1] + bias;
                    sPool[rl][(wn >> 1) + na * 4 + qtr] = fmaxf(vx, vy);
                }
            }
        }
    }
    __syncthreads();

    // ---- epilogue phase 2: upper-half (h0+1 row) combine + pooled store ---------
    if (wn >= 64) {
        const int p0 = (n0 >> 7) * 32;   // ph * 32
        #pragma unroll
        for (int ma = 0; ma < 2; ma++) {
            #pragma unroll
            for (int half = 0; half < 2; half++) {
                int rl = wm + ma * 16 + qid + half * 8;
                int m  = m0 + rl;
                if (m < 32) continue;    // q rows handled in phase 1
                float bias = g_bias[m];
                float* dst = (m < 64)
                    ? g_kp + ((size_t)b * C8 + (m - 32)) * DOWN
                    : g_vp + ((size_t)b * C2 + (m - 64)) * DOWN;
                #pragma unroll
                for (int na = 0; na < 4; na++) {
                    int pw = ((wn - 64) >> 1) + na * 4 + qtr;
                    float vx = acc[ma][na][half * 2 + 0] + bias;
                    float vy = acc[ma][na][half * 2 + 1] + bias;
                    float pm = fmaxf(fmaxf(vx, vy), sPool[rl][pw]);
                    dst[p0 + pw] = pm;
                }
            }
        }
    }
}

// ---------------- K3a: P = exp(Q @ K^T) stored bf16, tile 64l x 128j -------------
__global__ __launch_bounds__(256) void k_attn() {
    const int b  = blockIdx.z;
    const int l0 = blockIdx.y * 64;
    const int j0 = blockIdx.x * 128;

    const float* Q  = g_q  + (size_t)b * (C8 * HW);
    const float* Km = g_kp + (size_t)b * (C8 * DOWN);

    __shared__ float Qs[32][68];
    __shared__ float Ks[32][132];

    const int tid = threadIdx.x;
    const int tx = tid & 31;
    const int ty = tid >> 5;

    #pragma unroll
    for (int it = 0; it < 2; it++) {
        int idx = tid + it * 256;
        int lr = idx >> 3, lc = (idx & 7) * 4;
        float4 a = *(const float4*)&Q[(size_t)(l0 + lr) * 32 + lc];
        Qs[lc + 0][lr] = a.x; Qs[lc + 1][lr] = a.y;
        Qs[lc + 2][lr] = a.z; Qs[lc + 3][lr] = a.w;
    }
    #pragma unroll
    for (int it = 0; it < 4; it++) {
        int idx = tid + it * 256;
        int jr = idx >> 3, jc = (idx & 7) * 4;
        float4 k4 = *(const float4*)&Km[(size_t)(j0 + jr) * 32 + jc];
        Ks[jc + 0][jr] = k4.x; Ks[jc + 1][jr] = k4.y;
        Ks[jc + 2][jr] = k4.z; Ks[jc + 3][jr] = k4.w;
    }
    __syncthreads();

    float acc[8][4] = {};
    #pragma unroll
    for (int d = 0; d < 32; d++) {
        float a[8], bb[4];
        *(float4*)&a[0] = *(const float4*)&Qs[d][ty * 8];
        *(float4*)&a[4] = *(const float4*)&Qs[d][ty * 8 + 4];
        *(float4*)&bb[0] = *(const float4*)&Ks[d][tx * 4];
        #pragma unroll
        for (int i = 0; i < 8; i++)
            #pragma unroll
            for (int j = 0; j < 4; j++)
                acc[i][j] += a[i] * bb[j];
    }

    __nv_bfloat16* C = g_attn + ((size_t)b * HW + l0) * DOWN + j0;
    #pragma unroll
    for (int i = 0; i < 8; i++) {
        __nv_bfloat162 p0 = __floats2bfloat162_rn(__expf(acc[i][0]), __expf(acc[i][1]));
        __nv_bfloat162 p1 = __floats2bfloat162_rn(__expf(acc[i][2]), __expf(acc[i][3]));
        uint2 o;
        o.x = *(uint32_t*)&p0;
        o.y = *(uint32_t*)&p1;
        *(uint2*)&C[(size_t)(ty * 8 + i) * DOWN + tx * 4] = o;
    }
}

// ---------------- K3b: per-column partial sums of P (pure sum, bf16 in) ----------
__global__ void k_stats1() {
    const int b  = blockIdx.z;
    const int ck = blockIdx.y;
    const int j2 = blockIdx.x * 256 + threadIdx.x;   // column pair 0..511
    const int lsz = HW / NCHUNK;                     // 512
    const __nv_bfloat162* A = (const __nv_bfloat162*)(g_attn
        + (size_t)b * HW * DOWN + (size_t)ck * lsz * DOWN) + j2;
    float2 s0 = {0.f, 0.f}, s1 = {0.f, 0.f}, s2 = {0.f, 0.f}, s3 = {0.f, 0.f};
    #pragma unroll 2
    for (int l = 0; l < lsz; l += 4) {
        float2 a = __bfloat1622float2(A[(size_t)(l + 0) * (DOWN / 2)]);
        float2 bvv = __bfloat1622float2(A[(size_t)(l + 1) * (DOWN / 2)]);
        float2 c = __bfloat1622float2(A[(size_t)(l + 2) * (DOWN / 2)]);
        float2 d = __bfloat1622float2(A[(size_t)(l + 3) * (DOWN / 2)]);
        s0.x += a.x; s0.y += a.y;
        s1.x += bvv.x; s1.y += bvv.y;
        s2.x += c.x; s2.y += c.y;
        s3.x += d.x; s3.y += d.y;
    }
    float2 o;
    o.x = (s0.x + s1.x) + (s2.x + s3.x);
    o.y = (s0.y + s1.y) + (s2.y + s3.y);
    *(float2*)&g_ps[(b * NCHUNK + ck) * DOWN + j2 * 2] = o;
}

__global__ void k_stats2() {
    const int b = blockIdx.y;
    const int j = blockIdx.x * 256 + threadIdx.x;
    float S = 0.f;
    #pragma unroll
    for (int c = 0; c < NCHUNK; c++)
        S += g_ps[(b * NCHUNK + c) * DOWN + j];
    g_csumr[b * DOWN + j] = 1.f / S;
}

// ---------------- K4: applied = P @ (V/S) via mma.sync tf32 ----------------------
// P already exp'd in bf16; bf16->f32 is exact and tf32-valid (no cvt needed).
// Permuted-k smem layout: column j at PERM(j) = (j&3)*8 + (j>>2).
__global__ __launch_bounds__(256, 2) void k_apply_mma() {
    __shared__ float sP[128][36];   // [l][perm(j)]
    __shared__ float sB[128][36];   // [c][perm(j)]

    const int b   = blockIdx.y;
    const int l0  = blockIdx.x * 128;
    const int tid = threadIdx.x;
    const int wid = tid >> 5;
    const int lane = tid & 31;
    const int qid = lane >> 2;
    const int qtr = lane & 3;
    const int wm = (wid >> 2) * 64;
    const int wn = (wid & 3) * 32;

    const __nv_bfloat162* A = (const __nv_bfloat162*)(g_attn + ((size_t)b * HW + l0) * DOWN);
    const float* V  = g_vp   + (size_t)b * (C2 * DOWN);
    const float* cs = g_csumr + b * DOWN;

    float acc[4][4][4] = {};

    for (int j0 = 0; j0 < DOWN; j0 += 32) {
        #pragma unroll
        for (int it = 0; it < 4; it++) {
            int idx = tid + it * 256;
            int l = idx >> 3, a = idx & 7;
            const __nv_bfloat162* src = A + (size_t)l * (DOWN / 2) + (j0 >> 1) + a * 2;
            float2 f01 = __bfloat1622float2(src[0]);
            float2 f23 = __bfloat1622float2(src[1]);
            sP[l][a     ] = f01.x;
            sP[l][a + 8 ] = f01.y;
            sP[l][a + 16] = f23.x;
            sP[l][a + 24] = f23.y;
        }
        #pragma unroll
        for (int it = 0; it < 4; it++) {
            int idx = tid + it * 256;
            int c = idx & 127, j4 = idx >> 7;
            float4 s4 = *(const float4*)&cs[j0 + j4 * 4];
            sB[c][j4     ] = __uint_as_float(f2tf32(V[(size_t)(j0 + j4 * 4 + 0) * C2 + c] * s4.x));
            sB[c][j4 + 8 ] = __uint_as_float(f2tf32(V[(size_t)(j0 + j4 * 4 + 1) * C2 + c] * s4.y));
            sB[c][j4 + 16] = __uint_as_float(f2tf32(V[(size_t)(j0 + j4 * 4 + 2) * C2 + c] * s4.z));
            sB[c][j4 + 24] = __uint_as_float(f2tf32(V[(size_t)(j0 + j4 * 4 + 3) * C2 + c] * s4.w));
        }
        __syncthreads();

        #pragma unroll
        for (int p = 0; p < 2; p++) {
            float4 Bv[4];
            #pragma unroll
            for (int na = 0; na < 4; na++) {
                int c = wn + na * 8 + qid;
                Bv[na] = *(const float4*)&sB[c][qtr * 8 + p * 4];
            }
            #pragma unroll
            for (int ma = 0; ma < 4; ma++) {
                int r = wm + ma * 16 + qid;
                float4 Ar  = *(const float4*)&sP[r    ][qtr * 8 + p * 4];
                float4 Ar8 = *(const float4*)&sP[r + 8][qtr * 8 + p * 4];
                uint32_t afA[4] = {FU(Ar.x), FU(Ar8.x), FU(Ar.y), FU(Ar8.y)};
                uint32_t afB[4] = {FU(Ar.z), FU(Ar8.z), FU(Ar.w), FU(Ar8.w)};
                #pragma unroll
                for (int na = 0; na < 4; na++) {
                    uint32_t bfA[2] = {FU(Bv[na].x), FU(Bv[na].y)};
                    uint32_t bfB[2] = {FU(Bv[na].z), FU(Bv[na].w)};
                    mma_tf32(acc[ma][na], afA, bfA);
                    mma_tf32(acc[ma][na], afB, bfB);
                }
            }
        }
        __syncthreads();
    }

    float* O = g_app + ((size_t)b * HW + l0) * C2;
    #pragma unroll
    for (int ma = 0; ma < 4; ma++) {
        int r = wm + ma * 16 + qid;
        #pragma unroll
        for (int na = 0; na < 4; na++) {
            int c = wn + na * 8 + 2 * qtr;
            float2 lo, hi;
            lo.x = acc[ma][na][0]; lo.y = acc[ma][na][1];
            hi.x = acc[ma][na][2]; hi.y = acc[ma][na][3];
            *(float2*)&O[(size_t)r * C2 + c]       = lo;
            *(float2*)&O[(size_t)(r + 8) * C2 + c] = hi;
        }
    }
}

// ---------------- K5: out = gamma*(W2 @ applied_r + b2) + x via mma tf32 ---------
__global__ __launch_bounds__(256) void k_out_mma(const float* __restrict__ w2,
                                                 const float* __restrict__ b2,
                                                 const float* __restrict__ gamma,
                                                 const float* __restrict__ x,
                                                 float* __restrict__ out) {
    __shared__ float sA[64][36];
    __shared__ float sB[32][136];

    const int b  = blockIdx.z;
    const int m0 = blockIdx.y * 64;
    const int n0 = blockIdx.x * 128;
    const float* Bm = g_app + (size_t)b * (HW * C2);   // viewed [128][4096]

    const int tid  = threadIdx.x;
    const int wid  = tid >> 5;
    const int lane = tid & 31;
    const int qid  = lane >> 2;
    const int qtr  = lane & 3;
    const int wm   = (wid >> 2) * 32;
    const int wn   = (wid & 3) * 32;

    float acc[2][4][4] = {};

    for (int k0 = 0; k0 < C2; k0 += 32) {
        #pragma unroll
        for (int it = 0; it < 2; it++) {
            int f = tid + it * 256;
            int m = f >> 3, k4 = (f & 7) * 4;
            float4 a4 = *(const float4*)&w2[(m0 + m) * C2 + k0 + k4];
            uint32_t* dp = (uint32_t*)&sA[m][k4];
            dp[0] = f2tf32(a4.x); dp[1] = f2tf32(a4.y);
            dp[2] = f2tf32(a4.z); dp[3] = f2tf32(a4.w);
        }
        #pragma unroll
        for (int it = 0; it < 4; it++) {
            int f = tid + it * 256;
            int kk = f >> 5, n4 = (f & 31) * 4;
            float4 b4 = *(const float4*)&Bm[(size_t)(k0 + kk) * HW + n0 + n4];
            uint32_t* dp = (uint32_t*)&sB[kk][n4];
            dp[0] = f2tf32(b4.x); dp[1] = f2tf32(b4.y);
            dp[2] = f2tf32(b4.z); dp[3] = f2tf32(b4.w);
        }
        __syncthreads();

        #pragma unroll
        for (int ks = 0; ks < 4; ks++) {
            const int kk = ks * 8;
            uint32_t af[2][4], bf[4][2];
            #pragma unroll
            for (int ma = 0; ma < 2; ma++) {
                int r = wm + ma * 16 + qid;
                af[ma][0] = FU(sA[r    ][kk + qtr]);
                af[ma][1] = FU(sA[r + 8][kk + qtr]);
                af[ma][2] = FU(sA[r    ][kk + qtr + 4]);
                af[ma][3] = FU(sA[r + 8][kk + qtr + 4]);
            }
            #pragma unroll
            for (int na = 0; na < 4; na++) {
                int c = wn + na * 8 + qid;
                bf[na][0] = FU(sB[kk + qtr    ][c]);
                bf[na][1] = FU(sB[kk + qtr + 4][c]);
            }
            #pragma unroll
            for (int ma = 0; ma < 2; ma++)
                #pragma unroll
                for (int na = 0; na < 4; na++)
                    mma_tf32(acc[ma][na], af[ma], bf[na]);
        }
        __syncthreads();
    }

    const float g = __ldg(gamma);
    #pragma unroll
    for (int ma = 0; ma < 2; ma++) {
        #pragma unroll
        for (int half = 0; half < 2; half++) {
            int m = m0 + wm + ma * 16 + qid + half * 8;
            float bias = b2[m];
            #pragma unroll
            for (int na = 0; na < 4; na++) {
                int c = n0 + wn + na * 8 + 2 * qtr;
                size_t base = ((size_t)b * 256 + m) * HW + c;
                float2 xi = *(const float2*)&x[base];
                float2 o;
                o.x = g * (acc[ma][na][half * 2 + 0] + bias) + xi.x;
                o.y = g * (acc[ma][na][half * 2 + 1] + bias) + xi.y;
                *(float2*)&out[base] = o;
            }
        }
    }
}

// ---------------- launch ---------------------------------------------------------
extern "C" void kernel_launch(void* const* d_in, const int* in_sizes, int n_in,
                              void* d_out, int out_size) {
    const float* x  = (const float*)d_in[0];
    const float* qw = (const float*)d_in[1];
    const float* qb = (const float*)d_in[2];
    const float* kw = (const float*)d_in[3];
    const float* kb = (const float*)d_in[4];
    const float* vw = (const float*)d_in[5];
    const float* vb = (const float*)d_in[6];
    const float* w2 = (const float*)d_in[7];
    const float* b2 = (const float*)d_in[8];
    const float* gm = (const float*)d_in[9];
    float* out = (float*)d_out;

    k_pack<<<(MCONV * CIN + 255) / 256, 256>>>(qw, qb, kw, kb, vw, vb);
    k_conv_mma<<<dim3(HW / 128, MCONV / 64, BATCH), 256>>>(x);
    k_attn<<<dim3(DOWN / 128, HW / 64, BATCH), 256>>>();
    k_stats1<<<dim3(DOWN / 2 / 256, NCHUNK, BATCH), 256>>>();
    k_stats2<<<dim3(DOWN / 256, BATCH), 256>>>();
    k_apply_mma<<<dim3(HW / 128, BATCH), 256>>>();
    k_out_mma<<<dim3(HW / 128, 256 / 64, BATCH), 256>>>(w2, b2, gm, x, out);
}

// round 12
// speedup vs baseline: 1.1683x; 1.0409x over previous
#include <cuda_runtime.h>
#include <cuda_bf16.h>
#include <math.h>
#include <stdint.h>

#define BATCH 16
#define CIN   256
#define HW    4096      // 64*64
#define DOWN  1024      // 32*32
#define C8    32
#define C2    128
#define MCONV 192       // 32 + 32 + 128
#define NCHUNK 64       // l-chunks for column sum partials (64 rows each)

// ---------------- scratch (device globals; no allocation allowed) ----------------
__device__ float g_w   [MCONV * CIN];
__device__ float g_bias[MCONV];
__device__ float g_q   [BATCH * C8 * HW];
__device__ float g_kp  [BATCH * C8 * DOWN];
__device__ float g_vp  [BATCH * C2 * DOWN];
__device__ __nv_bfloat16 g_attn[(size_t)BATCH * HW * DOWN];  // 134 MB: P = exp(logit)
__device__ float g_ps  [BATCH * NCHUNK * DOWN];              // partial sums of P
__device__ float g_csumr[BATCH * DOWN];
__device__ float g_app [BATCH * HW * C2];

// ---------------- helpers --------------------------------------------------------
__device__ __forceinline__ uint32_t f2tf32(float v) {
    uint32_t r;
    asm("cvt.rna.tf32.f32 %0, %1;" : "=r"(r) : "f"(v));
    return r;
}
__device__ __forceinline__ void mma_tf32(float* d, const uint32_t* a, const uint32_t* b) {
    asm volatile(
        "mma.sync.aligned.m16n8k8.row.col.f32.tf32.tf32.f32 "
        "{%0,%1,%2,%3}, {%4,%5,%6,%7}, {%8,%9}, {%0,%1,%2,%3};"
        : "+f"(d[0]), "+f"(d[1]), "+f"(d[2]), "+f"(d[3])
        : "r"(a[0]), "r"(a[1]), "r"(a[2]), "r"(a[3]), "r"(b[0]), "r"(b[1]));
}
#define FU(x) __float_as_uint(x)

// ---------------- K0: pack conv weights ------------------------------------------
__global__ void k_pack(const float* __restrict__ qw, const float* __restrict__ qb,
                       const float* __restrict__ kw, const float* __restrict__ kb,
                       const float* __restrict__ vw, const float* __restrict__ vb) {
    int i = blockIdx.x * 256 + threadIdx.x;
    if (i < MCONV * CIN) {
        int r = i >> 8, c = i & 255;
        float v;
        if (r < 32)      v = qw[r * CIN + c];
        else if (r < 64) v = kw[(r - 32) * CIN + c];
        else             v = vw[(r - 64) * CIN + c];
        g_w[i] = v;
    }
    if (i < MCONV)
        g_bias[i] = (i < 32) ? qb[i] : (i < 64) ? kb[i - 32] : vb[i - 64];
}

// ---------------- K1: fused q/k/v convs + INLINE 2x2 MAXPOOL for k/v -------------
__global__ __launch_bounds__(256) void k_conv_mma(const float* __restrict__ x) {
    __shared__ float sA[64][36];    // W tile [m][k]
    __shared__ float sB[32][136];   // X tile [k][n]
    __shared__ float sPool[64][36]; // lower-half pair-max exchange

    const int b  = blockIdx.z;
    const int m0 = blockIdx.y * 64;
    const int n0 = blockIdx.x * 128;
    const float* X = x + (size_t)b * CIN * HW;

    const int tid  = threadIdx.x;
    const int wid  = tid >> 5;
    const int lane = tid & 31;
    const int qid  = lane >> 2;
    const int qtr  = lane & 3;
    const int wm   = (wid >> 2) * 32;
    const int wn   = (wid & 3) * 32;

    float acc[2][4][4] = {};

    for (int k0 = 0; k0 < CIN; k0 += 32) {
        #pragma unroll
        for (int it = 0; it < 2; it++) {
            int f = tid + it * 256;
            int m = f >> 3, k4 = (f & 7) * 4;
            float4 a4 = *(const float4*)&g_w[(m0 + m) * CIN + k0 + k4];
            uint32_t* dp = (uint32_t*)&sA[m][k4];
            dp[0] = f2tf32(a4.x); dp[1] = f2tf32(a4.y);
            dp[2] = f2tf32(a4.z); dp[3] = f2tf32(a4.w);
        }
        #pragma unroll
        for (int it = 0; it < 4; it++) {
            int f = tid + it * 256;
            int kk = f >> 5, n4 = (f & 31) * 4;
            float4 b4 = *(const float4*)&X[(size_t)(k0 + kk) * HW + n0 + n4];
            uint32_t* dp = (uint32_t*)&sB[kk][n4];
            dp[0] = f2tf32(b4.x); dp[1] = f2tf32(b4.y);
            dp[2] = f2tf32(b4.z); dp[3] = f2tf32(b4.w);
        }
        __syncthreads();

        #pragma unroll
        for (int ks = 0; ks < 4; ks++) {
            const int kk = ks * 8;
            uint32_t af[2][4], bf[4][2];
            #pragma unroll
            for (int ma = 0; ma < 2; ma++) {
                int r = wm + ma * 16 + qid;
                af[ma][0] = FU(sA[r    ][kk + qtr]);
                af[ma][1] = FU(sA[r + 8][kk + qtr]);
                af[ma][2] = FU(sA[r    ][kk + qtr + 4]);
                af[ma][3] = FU(sA[r + 8][kk + qtr + 4]);
            }
            #pragma unroll
            for (int na = 0; na < 4; na++) {
                int c = wn + na * 8 + qid;
                bf[na][0] = FU(sB[kk + qtr    ][c]);
                bf[na][1] = FU(sB[kk + qtr + 4][c]);
            }
            #pragma unroll
            for (int ma = 0; ma < 2; ma++)
                #pragma unroll
                for (int na = 0; na < 4; na++)
                    mma_tf32(acc[ma][na], af[ma], bf[na]);
        }
        __syncthreads();
    }

    // ---- epilogue phase 1: q direct stores + lower-half (h0 row) pool partials --
    #pragma unroll
    for (int ma = 0; ma < 2; ma++) {
        #pragma unroll
        for (int half = 0; half < 2; half++) {
            int rl = wm + ma * 16 + qid + half * 8;   // row in tile 0..63
            int m  = m0 + rl;
            float bias = g_bias[m];
            if (m < 32) {
                float* dst = g_q + ((size_t)b * C8 + m) * HW;
                #pragma unroll
                for (int na = 0; na < 4; na++) {
                    int c = n0 + wn + na * 8 + 2 * qtr;
                    float2 o;
                    o.x = acc[ma][na][half * 2 + 0] + bias;
                    o.y = acc[ma][na][half * 2 + 1] + bias;
                    *(float2*)&dst[c] = o;
                }
            } else if (wn < 64) {
                #pragma unroll
                for (int na = 0; na < 4; na++) {
                    float vx = acc[ma][na][half * 2 + 0] + bias;
                    float vy = acc[ma][na][half * 2 + 1] + bias;
                    sPool[rl][(wn >> 1) + na * 4 + qtr] = fmaxf(vx, vy);
                }
            }
        }
    }
    __syncthreads();

    // ---- epilogue phase 2: upper-half (h0+1 row) combine + pooled store ---------
    if (wn >= 64) {
        const int p0 = (n0 >> 7) * 32;   // ph * 32
        #pragma unroll
        for (int ma = 0; ma < 2; ma++) {
            #pragma unroll
            for (int half = 0; half < 2; half++) {
                int rl = wm + ma * 16 + qid + half * 8;
                int m  = m0 + rl;
                if (m < 32) continue;
                float bias = g_bias[m];
                float* dst = (m < 64)
                    ? g_kp + ((size_t)b * C8 + (m - 32)) * DOWN
                    : g_vp + ((size_t)b * C2 + (m - 64)) * DOWN;
                #pragma unroll
                for (int na = 0; na < 4; na++) {
                    int pw = ((wn - 64) >> 1) + na * 4 + qtr;
                    float vx = acc[ma][na][half * 2 + 0] + bias;
                    float vy = acc[ma][na][half * 2 + 1] + bias;
                    float pm = fmaxf(fmaxf(vx, vy), sPool[rl][pw]);
                    dst[p0 + pw] = pm;
                }
            }
        }
    }
}

// ---------------- K3a: P = exp(Q @ K^T) stored bf16, tile 64l x 128j -------------
__global__ __launch_bounds__(256) void k_attn() {
    const int b  = blockIdx.z;
    const int l0 = blockIdx.y * 64;
    const int j0 = blockIdx.x * 128;

    const float* Q  = g_q  + (size_t)b * (C8 * HW);
    const float* Km = g_kp + (size_t)b * (C8 * DOWN);

    __shared__ float Qs[32][68];
    __shared__ float Ks[32][132];

    const int tid = threadIdx.x;
    const int tx = tid & 31;
    const int ty = tid >> 5;

    #pragma unroll
    for (int it = 0; it < 2; it++) {
        int idx = tid + it * 256;
        int lr = idx >> 3, lc = (idx & 7) * 4;
        float4 a = *(const float4*)&Q[(size_t)(l0 + lr) * 32 + lc];
        Qs[lc + 0][lr] = a.x; Qs[lc + 1][lr] = a.y;
        Qs[lc + 2][lr] = a.z; Qs[lc + 3][lr] = a.w;
    }
    #pragma unroll
    for (int it = 0; it < 4; it++) {
        int idx = tid + it * 256;
        int jr = idx >> 3, jc = (idx & 7) * 4;
        float4 k4 = *(const float4*)&Km[(size_t)(j0 + jr) * 32 + jc];
        Ks[jc + 0][jr] = k4.x; Ks[jc + 1][jr] = k4.y;
        Ks[jc + 2][jr] = k4.z; Ks[jc + 3][jr] = k4.w;
    }
    __syncthreads();

    float acc[8][4] = {};
    #pragma unroll
    for (int d = 0; d < 32; d++) {
        float a[8], bb[4];
        *(float4*)&a[0] = *(const float4*)&Qs[d][ty * 8];
        *(float4*)&a[4] = *(const float4*)&Qs[d][ty * 8 + 4];
        *(float4*)&bb[0] = *(const float4*)&Ks[d][tx * 4];
        #pragma unroll
        for (int i = 0; i < 8; i++)
            #pragma unroll
            for (int j = 0; j < 4; j++)
                acc[i][j] += a[i] * bb[j];
    }

    __nv_bfloat16* C = g_attn + ((size_t)b * HW + l0) * DOWN + j0;
    #pragma unroll
    for (int i = 0; i < 8; i++) {
        __nv_bfloat162 p0 = __floats2bfloat162_rn(__expf(acc[i][0]), __expf(acc[i][1]));
        __nv_bfloat162 p1 = __floats2bfloat162_rn(__expf(acc[i][2]), __expf(acc[i][3]));
        uint2 o;
        o.x = *(uint32_t*)&p0;
        o.y = *(uint32_t*)&p1;
        *(uint2*)&C[(size_t)(ty * 8 + i) * DOWN + tx * 4] = o;
    }
}

// ---------------- K3b: per-column partial sums of P (pure sum, bf16 in) ----------
__global__ void k_stats1() {
    const int b  = blockIdx.z;
    const int ck = blockIdx.y;
    const int j2 = blockIdx.x * 256 + threadIdx.x;   // column pair 0..511
    const int lsz = HW / NCHUNK;                     // 64
    const __nv_bfloat162* A = (const __nv_bfloat162*)(g_attn
        + (size_t)b * HW * DOWN + (size_t)ck * lsz * DOWN) + j2;
    float2 s0 = {0.f, 0.f}, s1 = {0.f, 0.f}, s2 = {0.f, 0.f}, s3 = {0.f, 0.f};
    #pragma unroll 4
    for (int l = 0; l < lsz; l += 4) {
        float2 a = __bfloat1622float2(A[(size_t)(l + 0) * (DOWN / 2)]);
        float2 bvv = __bfloat1622float2(A[(size_t)(l + 1) * (DOWN / 2)]);
        float2 c = __bfloat1622float2(A[(size_t)(l + 2) * (DOWN / 2)]);
        float2 d = __bfloat1622float2(A[(size_t)(l + 3) * (DOWN / 2)]);
        s0.x += a.x; s0.y += a.y;
        s1.x += bvv.x; s1.y += bvv.y;
        s2.x += c.x; s2.y += c.y;
        s3.x += d.x; s3.y += d.y;
    }
    float2 o;
    o.x = (s0.x + s1.x) + (s2.x + s3.x);
    o.y = (s0.y + s1.y) + (s2.y + s3.y);
    *(float2*)&g_ps[(b * NCHUNK + ck) * DOWN + j2 * 2] = o;
}

__global__ void k_stats2() {
    const int b = blockIdx.y;
    const int j = blockIdx.x * 256 + threadIdx.x;
    float S = 0.f;
    #pragma unroll 8
    for (int c = 0; c < NCHUNK; c++)
        S += g_ps[(b * NCHUNK + c) * DOWN + j];
    g_csumr[b * DOWN + j] = 1.f / S;
}

// ---------------- K4: applied = P @ (V/S) via mma.sync tf32 ----------------------
__global__ __launch_bounds__(256, 2) void k_apply_mma() {
    __shared__ float sP[128][36];   // [l][perm(j)]
    __shared__ float sB[128][36];   // [c][perm(j)]

    const int b   = blockIdx.y;
    const int l0  = blockIdx.x * 128;
    const int tid = threadIdx.x;
    const int wid = tid >> 5;
    const int lane = tid & 31;
    const int qid = lane >> 2;
    const int qtr = lane & 3;
    const int wm = (wid >> 2) * 64;
    const int wn = (wid & 3) * 32;

    const __nv_bfloat162* A = (const __nv_bfloat162*)(g_attn + ((size_t)b * HW + l0) * DOWN);
    const float* V  = g_vp   + (size_t)b * (C2 * DOWN);
    const float* cs = g_csumr + b * DOWN;

    float acc[4][4][4] = {};

    for (int j0 = 0; j0 < DOWN; j0 += 32) {
        #pragma unroll
        for (int it = 0; it < 4; it++) {
            int idx = tid + it * 256;
            int l = idx >> 3, a = idx & 7;
            const __nv_bfloat162* src = A + (size_t)l * (DOWN / 2) + (j0 >> 1) + a * 2;
            float2 f01 = __bfloat1622float2(src[0]);
            float2 f23 = __bfloat1622float2(src[1]);
            sP[l][a     ] = f01.x;
            sP[l][a + 8 ] = f01.y;
            sP[l][a + 16] = f23.x;
            sP[l][a + 24] = f23.y;
        }
        #pragma unroll
        for (int it = 0; it < 4; it++) {
            int idx = tid + it * 256;
            int c = idx & 127, j4 = idx >> 7;
            float4 s4 = *(const float4*)&cs[j0 + j4 * 4];
            sB[c][j4     ] = __uint_as_float(f2tf32(V[(size_t)(j0 + j4 * 4 + 0) * C2 + c] * s4.x));
            sB[c][j4 + 8 ] = __uint_as_float(f2tf32(V[(size_t)(j0 + j4 * 4 + 1) * C2 + c] * s4.y));
            sB[c][j4 + 16] = __uint_as_float(f2tf32(V[(size_t)(j0 + j4 * 4 + 2) * C2 + c] * s4.z));
            sB[c][j4 + 24] = __uint_as_float(f2tf32(V[(size_t)(j0 + j4 * 4 + 3) * C2 + c] * s4.w));
        }
        __syncthreads();

        #pragma unroll
        for (int p = 0; p < 2; p++) {
            float4 Bv[4];
            #pragma unroll
            for (int na = 0; na < 4; na++) {
                int c = wn + na * 8 + qid;
                Bv[na] = *(const float4*)&sB[c][qtr * 8 + p * 4];
            }
            #pragma unroll
            for (int ma = 0; ma < 4; ma++) {
                int r = wm + ma * 16 + qid;
                float4 Ar  = *(const float4*)&sP[r    ][qtr * 8 + p * 4];
                float4 Ar8 = *(const float4*)&sP[r + 8][qtr * 8 + p * 4];
                uint32_t afA[4] = {FU(Ar.x), FU(Ar8.x), FU(Ar.y), FU(Ar8.y)};
                uint32_t afB[4] = {FU(Ar.z), FU(Ar8.z), FU(Ar.w), FU(Ar8.w)};
                #pragma unroll
                for (int na = 0; na < 4; na++) {
                    uint32_t bfA[2] = {FU(Bv[na].x), FU(Bv[na].y)};
                    uint32_t bfB[2] = {FU(Bv[na].z), FU(Bv[na].w)};
                    mma_tf32(acc[ma][na], afA, bfA);
                    mma_tf32(acc[ma][na], afB, bfB);
                }
            }
        }
        __syncthreads();
    }

    float* O = g_app + ((size_t)b * HW + l0) * C2;
    #pragma unroll
    for (int ma = 0; ma < 4; ma++) {
        int r = wm + ma * 16 + qid;
        #pragma unroll
        for (int na = 0; na < 4; na++) {
            int c = wn + na * 8 + 2 * qtr;
            float2 lo, hi;
            lo.x = acc[ma][na][0]; lo.y = acc[ma][na][1];
            hi.x = acc[ma][na][2]; hi.y = acc[ma][na][3];
            *(float2*)&O[(size_t)r * C2 + c]       = lo;
            *(float2*)&O[(size_t)(r + 8) * C2 + c] = hi;
        }
    }
}

// ---------------- K5: out = gamma*(W2 @ applied_r + b2) + x via mma tf32 ---------
__global__ __launch_bounds__(256) void k_out_mma(const float* __restrict__ w2,
                                                 const float* __restrict__ b2,
                                                 const float* __restrict__ gamma,
                                                 const float* __restrict__ x,
                                                 float* __restrict__ out) {
    __shared__ float sA[64][36];
    __shared__ float sB[32][136];

    const int b  = blockIdx.z;
    const int m0 = blockIdx.y * 64;
    const int n0 = blockIdx.x * 128;
    const float* Bm = g_app + (size_t)b * (HW * C2);   // viewed [128][4096]

    const int tid  = threadIdx.x;
    const int wid  = tid >> 5;
    const int lane = tid & 31;
    const int qid  = lane >> 2;
    const int qtr  = lane & 3;
    const int wm   = (wid >> 2) * 32;
    const int wn   = (wid & 3) * 32;

    float acc[2][4][4] = {};

    for (int k0 = 0; k0 < C2; k0 += 32) {
        #pragma unroll
        for (int it = 0; it < 2; it++) {
            int f = tid + it * 256;
            int m = f >> 3, k4 = (f & 7) * 4;
            float4 a4 = *(const float4*)&w2[(m0 + m) * C2 + k0 + k4];
            uint32_t* dp = (uint32_t*)&sA[m][k4];
            dp[0] = f2tf32(a4.x); dp[1] = f2tf32(a4.y);
            dp[2] = f2tf32(a4.z); dp[3] = f2tf32(a4.w);
        }
        #pragma unroll
        for (int it = 0; it < 4; it++) {
            int f = tid + it * 256;
            int kk = f >> 5, n4 = (f & 31) * 4;
            float4 b4 = *(const float4*)&Bm[(size_t)(k0 + kk) * HW + n0 + n4];
            uint32_t* dp = (uint32_t*)&sB[kk][n4];
            dp[0] = f2tf32(b4.x); dp[1] = f2tf32(b4.y);
            dp[2] = f2tf32(b4.z); dp[3] = f2tf32(b4.w);
        }
        __syncthreads();

        #pragma unroll
        for (int ks = 0; ks < 4; ks++) {
            const int kk = ks * 8;
            uint32_t af[2][4], bf[4][2];
            #pragma unroll
            for (int ma = 0; ma < 2; ma++) {
                int r = wm + ma * 16 + qid;
                af[ma][0] = FU(sA[r    ][kk + qtr]);
                af[ma][1] = FU(sA[r + 8][kk + qtr]);
                af[ma][2] = FU(sA[r    ][kk + qtr + 4]);
                af[ma][3] = FU(sA[r + 8][kk + qtr + 4]);
            }
            #pragma unroll
            for (int na = 0; na < 4; na++) {
                int c = wn + na * 8 + qid;
                bf[na][0] = FU(sB[kk + qtr    ][c]);
                bf[na][1] = FU(sB[kk + qtr + 4][c]);
            }
            #pragma unroll
            for (int ma = 0; ma < 2; ma++)
                #pragma unroll
                for (int na = 0; na < 4; na++)
                    mma_tf32(acc[ma][na], af[ma], bf[na]);
        }
        __syncthreads();
    }

    const float g = __ldg(gamma);
    #pragma unroll
    for (int ma = 0; ma < 2; ma++) {
        #pragma unroll
        for (int half = 0; half < 2; half++) {
            int m = m0 + wm + ma * 16 + qid + half * 8;
            float bias = b2[m];
            #pragma unroll
            for (int na = 0; na < 4; na++) {
                int c = n0 + wn + na * 8 + 2 * qtr;
                size_t base = ((size_t)b * 256 + m) * HW + c;
                float2 xi = *(const float2*)&x[base];
                float2 o;
                o.x = g * (acc[ma][na][half * 2 + 0] + bias) + xi.x;
                o.y = g * (acc[ma][na][half * 2 + 1] + bias) + xi.y;
                *(float2*)&out[base] = o;
            }
        }
    }
}

// ---------------- launch ---------------------------------------------------------
extern "C" void kernel_launch(void* const* d_in, const int* in_sizes, int n_in,
                              void* d_out, int out_size) {
    const float* x  = (const float*)d_in[0];
    const float* qw = (const float*)d_in[1];
    const float* qb = (const float*)d_in[2];
    const float* kw = (const float*)d_in[3];
    const float* kb = (const float*)d_in[4];
    const float* vw = (const float*)d_in[5];
    const float* vb = (const float*)d_in[6];
    const float* w2 = (const float*)d_in[7];
    const float* b2 = (const float*)d_in[8];
    const float* gm = (const float*)d_in[9];
    float* out = (float*)d_out;

    k_pack<<<(MCONV * CIN + 255) / 256, 256>>>(qw, qb, kw, kb, vw, vb);
    k_conv_mma<<<dim3(HW / 128, MCONV / 64, BATCH), 256>>>(x);
    k_attn<<<dim3(DOWN / 128, HW / 64, BATCH), 256>>>();
    k_stats1<<<dim3(DOWN / 2 / 256, NCHUNK, BATCH), 256>>>();
    k_stats2<<<dim3(DOWN / 256, BATCH), 256>>>();
    k_apply_mma<<<dim3(HW / 128, BATCH), 256>>>();
    k_out_mma<<<dim3(HW / 128, 256 / 64, BATCH), 256>>>(w2, b2, gm, x, out);
}

// round 13
// speedup vs baseline: 1.3694x; 1.1721x over previous
#include <cuda_runtime.h>
#include <cuda_bf16.h>
#include <math.h>
#include <stdint.h>

#define BATCH 16
#define CIN   256
#define HW    4096      // 64*64
#define DOWN  1024      // 32*32
#define C8    32
#define C2    128
#define MCONV 192       // 32 + 32 + 128
#define NCHUNK 64       // l-chunks for column sum partials (64 rows each)

// ---------------- scratch (device globals; no allocation allowed) ----------------
__device__ float g_w   [MCONV * CIN];
__device__ float g_bias[MCONV];
__device__ float g_q   [BATCH * C8 * HW];
__device__ float g_kp  [BATCH * C8 * DOWN];
__device__ float g_vp  [BATCH * C2 * DOWN];
__device__ __nv_bfloat16 g_attn[(size_t)BATCH * HW * DOWN];  // 134 MB: P = exp(logit)
__device__ float g_ps  [BATCH * NCHUNK * DOWN];              // partial sums of P
__device__ float g_csumr[BATCH * DOWN];
__device__ float g_app [BATCH * HW * C2];

// ---------------- helpers --------------------------------------------------------
__device__ __forceinline__ uint32_t f2tf32(float v) {
    uint32_t r;
    asm("cvt.rna.tf32.f32 %0, %1;" : "=r"(r) : "f"(v));
    return r;
}
__device__ __forceinline__ void mma_tf32(float* d, const uint32_t* a, const uint32_t* b) {
    asm volatile(
        "mma.sync.aligned.m16n8k8.row.col.f32.tf32.tf32.f32 "
        "{%0,%1,%2,%3}, {%4,%5,%6,%7}, {%8,%9}, {%0,%1,%2,%3};"
        : "+f"(d[0]), "+f"(d[1]), "+f"(d[2]), "+f"(d[3])
        : "r"(a[0]), "r"(a[1]), "r"(a[2]), "r"(a[3]), "r"(b[0]), "r"(b[1]));
}
__device__ __forceinline__ void mma_bf16(float* d, const uint32_t* a, const uint32_t* b) {
    asm volatile(
        "mma.sync.aligned.m16n8k16.row.col.f32.bf16.bf16.f32 "
        "{%0,%1,%2,%3}, {%4,%5,%6,%7}, {%8,%9}, {%0,%1,%2,%3};"
        : "+f"(d[0]), "+f"(d[1]), "+f"(d[2]), "+f"(d[3])
        : "r"(a[0]), "r"(a[1]), "r"(a[2]), "r"(a[3]), "r"(b[0]), "r"(b[1]));
}
#define FU(x) __float_as_uint(x)

// ---------------- K0: pack conv weights ------------------------------------------
__global__ void k_pack(const float* __restrict__ qw, const float* __restrict__ qb,
                       const float* __restrict__ kw, const float* __restrict__ kb,
                       const float* __restrict__ vw, const float* __restrict__ vb) {
    int i = blockIdx.x * 256 + threadIdx.x;
    if (i < MCONV * CIN) {
        int r = i >> 8, c = i & 255;
        float v;
        if (r < 32)      v = qw[r * CIN + c];
        else if (r < 64) v = kw[(r - 32) * CIN + c];
        else             v = vw[(r - 64) * CIN + c];
        g_w[i] = v;
    }
    if (i < MCONV)
        g_bias[i] = (i < 32) ? qb[i] : (i < 64) ? kb[i - 32] : vb[i - 64];
}

// ---------------- K1: fused q/k/v convs + INLINE 2x2 MAXPOOL for k/v -------------
__global__ __launch_bounds__(256) void k_conv_mma(const float* __restrict__ x) {
    __shared__ float sA[64][36];    // W tile [m][k]
    __shared__ float sB[32][136];   // X tile [k][n]
    __shared__ float sPool[64][36]; // lower-half pair-max exchange

    const int b  = blockIdx.z;
    const int m0 = blockIdx.y * 64;
    const int n0 = blockIdx.x * 128;
    const float* X = x + (size_t)b * CIN * HW;

    const int tid  = threadIdx.x;
    const int wid  = tid >> 5;
    const int lane = tid & 31;
    const int qid  = lane >> 2;
    const int qtr  = lane & 3;
    const int wm   = (wid >> 2) * 32;
    const int wn   = (wid & 3) * 32;

    float acc[2][4][4] = {};

    for (int k0 = 0; k0 < CIN; k0 += 32) {
        #pragma unroll
        for (int it = 0; it < 2; it++) {
            int f = tid + it * 256;
            int m = f >> 3, k4 = (f & 7) * 4;
            float4 a4 = *(const float4*)&g_w[(m0 + m) * CIN + k0 + k4];
            uint32_t* dp = (uint32_t*)&sA[m][k4];
            dp[0] = f2tf32(a4.x); dp[1] = f2tf32(a4.y);
            dp[2] = f2tf32(a4.z); dp[3] = f2tf32(a4.w);
        }
        #pragma unroll
        for (int it = 0; it < 4; it++) {
            int f = tid + it * 256;
            int kk = f >> 5, n4 = (f & 31) * 4;
            float4 b4 = *(const float4*)&X[(size_t)(k0 + kk) * HW + n0 + n4];
            uint32_t* dp = (uint32_t*)&sB[kk][n4];
            dp[0] = f2tf32(b4.x); dp[1] = f2tf32(b4.y);
            dp[2] = f2tf32(b4.z); dp[3] = f2tf32(b4.w);
        }
        __syncthreads();

        #pragma unroll
        for (int ks = 0; ks < 4; ks++) {
            const int kk = ks * 8;
            uint32_t af[2][4], bf[4][2];
            #pragma unroll
            for (int ma = 0; ma < 2; ma++) {
                int r = wm + ma * 16 + qid;
                af[ma][0] = FU(sA[r    ][kk + qtr]);
                af[ma][1] = FU(sA[r + 8][kk + qtr]);
                af[ma][2] = FU(sA[r    ][kk + qtr + 4]);
                af[ma][3] = FU(sA[r + 8][kk + qtr + 4]);
            }
            #pragma unroll
            for (int na = 0; na < 4; na++) {
                int c = wn + na * 8 + qid;
                bf[na][0] = FU(sB[kk + qtr    ][c]);
                bf[na][1] = FU(sB[kk + qtr + 4][c]);
            }
            #pragma unroll
            for (int ma = 0; ma < 2; ma++)
                #pragma unroll
                for (int na = 0; na < 4; na++)
                    mma_tf32(acc[ma][na], af[ma], bf[na]);
        }
        __syncthreads();
    }

    // ---- epilogue phase 1: q direct stores + lower-half (h0 row) pool partials --
    #pragma unroll
    for (int ma = 0; ma < 2; ma++) {
        #pragma unroll
        for (int half = 0; half < 2; half++) {
            int rl = wm + ma * 16 + qid + half * 8;   // row in tile 0..63
            int m  = m0 + rl;
            float bias = g_bias[m];
            if (m < 32) {
                float* dst = g_q + ((size_t)b * C8 + m) * HW;
                #pragma unroll
                for (int na = 0; na < 4; na++) {
                    int c = n0 + wn + na * 8 + 2 * qtr;
                    float2 o;
                    o.x = acc[ma][na][half * 2 + 0] + bias;
                    o.y = acc[ma][na][half * 2 + 1] + bias;
                    *(float2*)&dst[c] = o;
                }
            } else if (wn < 64) {
                #pragma unroll
                for (int na = 0; na < 4; na++) {
                    float vx = acc[ma][na][half * 2 + 0] + bias;
                    float vy = acc[ma][na][half * 2 + 1] + bias;
                    sPool[rl][(wn >> 1) + na * 4 + qtr] = fmaxf(vx, vy);
                }
            }
        }
    }
    __syncthreads();

    // ---- epilogue phase 2: upper-half (h0+1 row) combine + pooled store ---------
    if (wn >= 64) {
        const int p0 = (n0 >> 7) * 32;   // ph * 32
        #pragma unroll
        for (int ma = 0; ma < 2; ma++) {
            #pragma unroll
            for (int half = 0; half < 2; half++) {
                int rl = wm + ma * 16 + qid + half * 8;
                int m  = m0 + rl;
                if (m < 32) continue;
                float bias = g_bias[m];
                float* dst = (m < 64)
                    ? g_kp + ((size_t)b * C8 + (m - 32)) * DOWN
                    : g_vp + ((size_t)b * C2 + (m - 64)) * DOWN;
                #pragma unroll
                for (int na = 0; na < 4; na++) {
                    int pw = ((wn - 64) >> 1) + na * 4 + qtr;
                    float vx = acc[ma][na][half * 2 + 0] + bias;
                    float vy = acc[ma][na][half * 2 + 1] + bias;
                    float pm = fmaxf(fmaxf(vx, vy), sPool[rl][pw]);
                    dst[p0 + pw] = pm;
                }
            }
        }
    }
}

// ---------------- K3a: P = exp(Q @ K^T) stored bf16, tile 64l x 128j -------------
__global__ __launch_bounds__(256) void k_attn() {
    const int b  = blockIdx.z;
    const int l0 = blockIdx.y * 64;
    const int j0 = blockIdx.x * 128;

    const float* Q  = g_q  + (size_t)b * (C8 * HW);
    const float* Km = g_kp + (size_t)b * (C8 * DOWN);

    __shared__ float Qs[32][68];
    __shared__ float Ks[32][132];

    const int tid = threadIdx.x;
    const int tx = tid & 31;
    const int ty = tid >> 5;

    #pragma unroll
    for (int it = 0; it < 2; it++) {
        int idx = tid + it * 256;
        int lr = idx >> 3, lc = (idx & 7) * 4;
        float4 a = *(const float4*)&Q[(size_t)(l0 + lr) * 32 + lc];
        Qs[lc + 0][lr] = a.x; Qs[lc + 1][lr] = a.y;
        Qs[lc + 2][lr] = a.z; Qs[lc + 3][lr] = a.w;
    }
    #pragma unroll
    for (int it = 0; it < 4; it++) {
        int idx = tid + it * 256;
        int jr = idx >> 3, jc = (idx & 7) * 4;
        float4 k4 = *(const float4*)&Km[(size_t)(j0 + jr) * 32 + jc];
        Ks[jc + 0][jr] = k4.x; Ks[jc + 1][jr] = k4.y;
        Ks[jc + 2][jr] = k4.z; Ks[jc + 3][jr] = k4.w;
    }
    __syncthreads();

    float acc[8][4] = {};
    #pragma unroll
    for (int d = 0; d < 32; d++) {
        float a[8], bb[4];
        *(float4*)&a[0] = *(const float4*)&Qs[d][ty * 8];
        *(float4*)&a[4] = *(const float4*)&Qs[d][ty * 8 + 4];
        *(float4*)&bb[0] = *(const float4*)&Ks[d][tx * 4];
        #pragma unroll
        for (int i = 0; i < 8; i++)
            #pragma unroll
            for (int j = 0; j < 4; j++)
                acc[i][j] += a[i] * bb[j];
    }

    __nv_bfloat16* C = g_attn + ((size_t)b * HW + l0) * DOWN + j0;
    #pragma unroll
    for (int i = 0; i < 8; i++) {
        __nv_bfloat162 p0 = __floats2bfloat162_rn(__expf(acc[i][0]), __expf(acc[i][1]));
        __nv_bfloat162 p1 = __floats2bfloat162_rn(__expf(acc[i][2]), __expf(acc[i][3]));
        uint2 o;
        o.x = *(uint32_t*)&p0;
        o.y = *(uint32_t*)&p1;
        *(uint2*)&C[(size_t)(ty * 8 + i) * DOWN + tx * 4] = o;
    }
}

// ---------------- K3b: per-column partial sums of P (pure sum, bf16 in) ----------
__global__ void k_stats1() {
    const int b  = blockIdx.z;
    const int ck = blockIdx.y;
    const int j2 = blockIdx.x * 256 + threadIdx.x;   // column pair 0..511
    const int lsz = HW / NCHUNK;                     // 64
    const __nv_bfloat162* A = (const __nv_bfloat162*)(g_attn
        + (size_t)b * HW * DOWN + (size_t)ck * lsz * DOWN) + j2;
    float2 s0 = {0.f, 0.f}, s1 = {0.f, 0.f}, s2 = {0.f, 0.f}, s3 = {0.f, 0.f};
    #pragma unroll 4
    for (int l = 0; l < lsz; l += 4) {
        float2 a = __bfloat1622float2(A[(size_t)(l + 0) * (DOWN / 2)]);
        float2 bvv = __bfloat1622float2(A[(size_t)(l + 1) * (DOWN / 2)]);
        float2 c = __bfloat1622float2(A[(size_t)(l + 2) * (DOWN / 2)]);
        float2 d = __bfloat1622float2(A[(size_t)(l + 3) * (DOWN / 2)]);
        s0.x += a.x; s0.y += a.y;
        s1.x += bvv.x; s1.y += bvv.y;
        s2.x += c.x; s2.y += c.y;
        s3.x += d.x; s3.y += d.y;
    }
    float2 o;
    o.x = (s0.x + s1.x) + (s2.x + s3.x);
    o.y = (s0.y + s1.y) + (s2.y + s3.y);
    *(float2*)&g_ps[(b * NCHUNK + ck) * DOWN + j2 * 2] = o;
}

__global__ void k_stats2() {
    const int b = blockIdx.y;
    const int j = blockIdx.x * 256 + threadIdx.x;
    float S = 0.f;
    #pragma unroll 8
    for (int c = 0; c < NCHUNK; c++)
        S += g_ps[(b * NCHUNK + c) * DOWN + j];
    g_csumr[b * DOWN + j] = 1.f / S;
}

// ---------------- K4: applied = P @ (V/S) via mma.sync bf16 m16n8k16 -------------
// P is already bf16 in gmem (A operand native). B = bf16(V * csumr).
// sP/sB rows padded to 40 bf16 (80B) -> fragment loads provably conflict-free.
__global__ __launch_bounds__(256, 2) void k_apply_mma() {
    __shared__ __nv_bfloat16 sP[128][40];   // [l][j in chunk]
    __shared__ __nv_bfloat16 sB[128][40];   // [c][j in chunk]

    const int b   = blockIdx.y;
    const int l0  = blockIdx.x * 128;
    const int tid = threadIdx.x;
    const int wid = tid >> 5;
    const int lane = tid & 31;
    const int qid = lane >> 2;
    const int qtr = lane & 3;
    const int wm = (wid >> 2) * 64;
    const int wn = (wid & 3) * 32;

    const __nv_bfloat16* A = g_attn + ((size_t)b * HW + l0) * DOWN;
    const float* V  = g_vp   + (size_t)b * (C2 * DOWN);
    const float* cs = g_csumr + b * DOWN;

    float acc[4][4][4] = {};

    for (int j0 = 0; j0 < DOWN; j0 += 32) {
        // stage P: pure bf16 copy (8 KB)
        #pragma unroll
        for (int it = 0; it < 4; it++) {
            int idx = tid + it * 256;
            int l = idx >> 3, jq = (idx & 7) * 4;
            uint2 v = *(const uint2*)&A[(size_t)l * DOWN + j0 + jq];
            *(uint2*)&sP[l][jq] = v;
        }
        // stage B[c][j] = bf16(V[j][c] * csumr[j])
        #pragma unroll
        for (int it = 0; it < 4; it++) {
            int idx = tid + it * 256;
            int c = idx & 127, j4 = idx >> 7;     // j4 in 0..7
            float4 s4 = *(const float4*)&cs[j0 + j4 * 4];
            __nv_bfloat162 p0 = __floats2bfloat162_rn(
                V[(size_t)(j0 + j4 * 4 + 0) * C2 + c] * s4.x,
                V[(size_t)(j0 + j4 * 4 + 1) * C2 + c] * s4.y);
            __nv_bfloat162 p1 = __floats2bfloat162_rn(
                V[(size_t)(j0 + j4 * 4 + 2) * C2 + c] * s4.z,
                V[(size_t)(j0 + j4 * 4 + 3) * C2 + c] * s4.w);
            uint2 o;
            o.x = *(uint32_t*)&p0;
            o.y = *(uint32_t*)&p1;
            *(uint2*)&sB[c][j4 * 4] = o;
        }
        __syncthreads();

        #pragma unroll
        for (int ks = 0; ks < 2; ks++) {
            const int kb = ks * 16;
            uint32_t bfr[4][2];
            #pragma unroll
            for (int na = 0; na < 4; na++) {
                int c = wn + na * 8 + qid;
                bfr[na][0] = *(const uint32_t*)&sB[c][kb + qtr * 2];
                bfr[na][1] = *(const uint32_t*)&sB[c][kb + 8 + qtr * 2];
            }
            #pragma unroll
            for (int ma = 0; ma < 4; ma++) {
                int r = wm + ma * 16 + qid;
                uint32_t af[4];
                af[0] = *(const uint32_t*)&sP[r    ][kb + qtr * 2];
                af[1] = *(const uint32_t*)&sP[r + 8][kb + qtr * 2];
                af[2] = *(const uint32_t*)&sP[r    ][kb + 8 + qtr * 2];
                af[3] = *(const uint32_t*)&sP[r + 8][kb + 8 + qtr * 2];
                #pragma unroll
                for (int na = 0; na < 4; na++)
                    mma_bf16(acc[ma][na], af, bfr[na]);
            }
        }
        __syncthreads();
    }

    float* O = g_app + ((size_t)b * HW + l0) * C2;
    #pragma unroll
    for (int ma = 0; ma < 4; ma++) {
        int r = wm + ma * 16 + qid;
        #pragma unroll
        for (int na = 0; na < 4; na++) {
            int c = wn + na * 8 + 2 * qtr;
            float2 lo, hi;
            lo.x = acc[ma][na][0]; lo.y = acc[ma][na][1];
            hi.x = acc[ma][na][2]; hi.y = acc[ma][na][3];
            *(float2*)&O[(size_t)r * C2 + c]       = lo;
            *(float2*)&O[(size_t)(r + 8) * C2 + c] = hi;
        }
    }
}

// ---------------- K5: out = gamma*(W2 @ applied_r + b2) + x via mma tf32 ---------
__global__ __launch_bounds__(256) void k_out_mma(const float* __restrict__ w2,
                                                 const float* __restrict__ b2,
                                                 const float* __restrict__ gamma,
                                                 const float* __restrict__ x,
                                                 float* __restrict__ out) {
    __shared__ float sA[64][36];
    __shared__ float sB[32][136];

    const int b  = blockIdx.z;
    const int m0 = blockIdx.y * 64;
    const int n0 = blockIdx.x * 128;
    const float* Bm = g_app + (size_t)b * (HW * C2);   // viewed [128][4096]

    const int tid  = threadIdx.x;
    const int wid  = tid >> 5;
    const int lane = tid & 31;
    const int qid  = lane >> 2;
    const int qtr  = lane & 3;
    const int wm   = (wid >> 2) * 32;
    const int wn   = (wid & 3) * 32;

    float acc[2][4][4] = {};

    for (int k0 = 0; k0 < C2; k0 += 32) {
        #pragma unroll
        for (int it = 0; it < 2; it++) {
            int f = tid + it * 256;
            int m = f >> 3, k4 = (f & 7) * 4;
            float4 a4 = *(const float4*)&w2[(m0 + m) * C2 + k0 + k4];
            uint32_t* dp = (uint32_t*)&sA[m][k4];
            dp[0] = f2tf32(a4.x); dp[1] = f2tf32(a4.y);
            dp[2] = f2tf32(a4.z); dp[3] = f2tf32(a4.w);
        }
        #pragma unroll
        for (int it = 0; it < 4; it++) {
            int f = tid + it * 256;
            int kk = f >> 5, n4 = (f & 31) * 4;
            float4 b4 = *(const float4*)&Bm[(size_t)(k0 + kk) * HW + n0 + n4];
            uint32_t* dp = (uint32_t*)&sB[kk][n4];
            dp[0] = f2tf32(b4.x); dp[1] = f2tf32(b4.y);
            dp[2] = f2tf32(b4.z); dp[3] = f2tf32(b4.w);
        }
        __syncthreads();

        #pragma unroll
        for (int ks = 0; ks < 4; ks++) {
            const int kk = ks * 8;
            uint32_t af[2][4], bf[4][2];
            #pragma unroll
            for (int ma = 0; ma < 2; ma++) {
                int r = wm + ma * 16 + qid;
                af[ma][0] = FU(sA[r    ][kk + qtr]);
                af[ma][1] = FU(sA[r + 8][kk + qtr]);
                af[ma][2] = FU(sA[r    ][kk + qtr + 4]);
                af[ma][3] = FU(sA[r + 8][kk + qtr + 4]);
            }
            #pragma unroll
            for (int na = 0; na < 4; na++) {
                int c = wn + na * 8 + qid;
                bf[na][0] = FU(sB[kk + qtr    ][c]);
                bf[na][1] = FU(sB[kk + qtr + 4][c]);
            }
            #pragma unroll
            for (int ma = 0; ma < 2; ma++)
                #pragma unroll
                for (int na = 0; na < 4; na++)
                    mma_tf32(acc[ma][na], af[ma], bf[na]);
        }
        __syncthreads();
    }

    const float g = __ldg(gamma);
    #pragma unroll
    for (int ma = 0; ma < 2; ma++) {
        #pragma unroll
        for (int half = 0; half < 2; half++) {
            int m = m0 + wm + ma * 16 + qid + half * 8;
            float bias = b2[m];
            #pragma unroll
            for (int na = 0; na < 4; na++) {
                int c = n0 + wn + na * 8 + 2 * qtr;
                size_t base = ((size_t)b * 256 + m) * HW + c;
                float2 xi = *(const float2*)&x[base];
                float2 o;
                o.x = g * (acc[ma][na][half * 2 + 0] + bias) + xi.x;
                o.y = g * (acc[ma][na][half * 2 + 1] + bias) + xi.y;
                *(float2*)&out[base] = o;
            }
        }
    }
}

// ---------------- launch ---------------------------------------------------------
extern "C" void kernel_launch(void* const* d_in, const int* in_sizes, int n_in,
                              void* d_out, int out_size) {
    const float* x  = (const float*)d_in[0];
    const float* qw = (const float*)d_in[1];
    const float* qb = (const float*)d_in[2];
    const float* kw = (const float*)d_in[3];
    const float* kb = (const float*)d_in[4];
    const float* vw = (const float*)d_in[5];
    const float* vb = (const float*)d_in[6];
    const float* w2 = (const float*)d_in[7];
    const float* b2 = (const float*)d_in[8];
    const float* gm = (const float*)d_in[9];
    float* out = (float*)d_out;

    k_pack<<<(MCONV * CIN + 255) / 256, 256>>>(qw, qb, kw, kb, vw, vb);
    k_conv_mma<<<dim3(HW / 128, MCONV / 64, BATCH), 256>>>(x);
    k_attn<<<dim3(DOWN / 128, HW / 64, BATCH), 256>>>();
    k_stats1<<<dim3(DOWN / 2 / 256, NCHUNK, BATCH), 256>>>();
    k_stats2<<<dim3(DOWN / 256, BATCH), 256>>>();
    k_apply_mma<<<dim3(HW / 128, BATCH), 256>>>();
    k_out_mma<<<dim3(HW / 128, 256 / 64, BATCH), 256>>>(w2, b2, gm, x, out);
}